// round 3
// baseline (speedup 1.0000x reference)
#include <cuda_runtime.h>
#include <cuda_bf16.h>
#include <math.h>

// Problem constants
#define BB 128
#define NN 2048
#define EE 128
#define MT (BB * NN)   // 262144 total rows

// ---------------- scratch (device globals; no allocation allowed) -----------
__device__ float g_proj[(size_t)MT * EE];   // [M,128]
__device__ float g_X1b [(size_t)MT * EE];   // W_c1*proj + b_c
__device__ float g_X2  [(size_t)MT * EE];   // W_c2*proj
__device__ float g_ut  [MT];
__device__ float g_at  [MT];
__device__ float g_ut2 [MT];
__device__ float g_prob[MT];
__device__ float g_hi  [BB * EE];

// ---------------- K1a: proj = X * Ws^T + bs  (tile 128x128, K=128) ----------
__global__ __launch_bounds__(256) void gemm_proj(
    const float* __restrict__ X,   // [M,128]
    const float* __restrict__ Ws,  // [128,128] row-major [e][s]
    const float* __restrict__ bs)  // [128]
{
    __shared__ float As[8][128];
    __shared__ float Bs[8][128];
    const int row0 = blockIdx.x * 128;
    const int tid = threadIdx.x;
    const int tx = tid & 15, ty = tid >> 4;
    const int lm = tid >> 1;            // 0..127
    const int lk = (tid & 1) * 4;       // 0 or 4

    float acc[8][8];
    #pragma unroll
    for (int i = 0; i < 8; i++)
        #pragma unroll
        for (int j = 0; j < 8; j++) acc[i][j] = 0.f;

    const float* Xp = X + (size_t)(row0 + lm) * 128 + lk;
    const float* Wp = Ws + lm * 128 + lk;

    for (int k0 = 0; k0 < 128; k0 += 8) {
        float4 a = *(const float4*)(Xp + k0);
        float4 b = *(const float4*)(Wp + k0);
        As[lk + 0][lm] = a.x; As[lk + 1][lm] = a.y;
        As[lk + 2][lm] = a.z; As[lk + 3][lm] = a.w;
        Bs[lk + 0][lm] = b.x; Bs[lk + 1][lm] = b.y;
        Bs[lk + 2][lm] = b.z; Bs[lk + 3][lm] = b.w;
        __syncthreads();
        #pragma unroll
        for (int kk = 0; kk < 8; kk++) {
            float4 a0 = *(const float4*)&As[kk][ty * 4];
            float4 a1 = *(const float4*)&As[kk][64 + ty * 4];
            float4 b0 = *(const float4*)&Bs[kk][tx * 4];
            float4 b1 = *(const float4*)&Bs[kk][64 + tx * 4];
            float am[8] = {a0.x, a0.y, a0.z, a0.w, a1.x, a1.y, a1.z, a1.w};
            float bn[8] = {b0.x, b0.y, b0.z, b0.w, b1.x, b1.y, b1.z, b1.w};
            #pragma unroll
            for (int i = 0; i < 8; i++)
                #pragma unroll
                for (int j = 0; j < 8; j++)
                    acc[i][j] = fmaf(am[i], bn[j], acc[i][j]);
        }
        __syncthreads();
    }

    float breg[8];
    #pragma unroll
    for (int j = 0; j < 8; j++) {
        int c = (j < 4) ? (tx * 4 + j) : (64 + tx * 4 + (j - 4));
        breg[j] = bs[c];
    }
    #pragma unroll
    for (int i = 0; i < 8; i++) {
        int m = (i < 4) ? (ty * 4 + i) : (64 + ty * 4 + (i - 4));
        float* outp = g_proj + (size_t)(row0 + m) * 128;
        float4 v0, v1;
        v0.x = acc[i][0] + breg[0]; v0.y = acc[i][1] + breg[1];
        v0.z = acc[i][2] + breg[2]; v0.w = acc[i][3] + breg[3];
        v1.x = acc[i][4] + breg[4]; v1.y = acc[i][5] + breg[5];
        v1.z = acc[i][6] + breg[6]; v1.w = acc[i][7] + breg[7];
        *(float4*)(outp + tx * 4)      = v0;
        *(float4*)(outp + 64 + tx * 4) = v1;
    }
}

// ---------------- K1b: Y = proj * Wcat^T; 3 chunks (Wa / Wc1 / Wc2) --------
__global__ __launch_bounds__(256) void gemm_attn(
    const float* __restrict__ Wa,   // [128][128]
    const float* __restrict__ ba,   // [128]
    const float* __restrict__ va,   // [128]
    const float* __restrict__ Wc,   // [128][256]
    const float* __restrict__ bc)   // [128]
{
    __shared__ float As[8][128];
    __shared__ float Bs[8][128];
    __shared__ float red[128][17];
    const int chunk = blockIdx.y;           // 0: Wa, 1: Wc[:, :128], 2: Wc[:, 128:]
    const int row0 = blockIdx.x * 128;
    const int tid = threadIdx.x;
    const int tx = tid & 15, ty = tid >> 4;
    const int lm = tid >> 1;
    const int lk = (tid & 1) * 4;

    float acc[8][8];
    #pragma unroll
    for (int i = 0; i < 8; i++)
        #pragma unroll
        for (int j = 0; j < 8; j++) acc[i][j] = 0.f;

    const float* Ap = g_proj + (size_t)(row0 + lm) * 128 + lk;
    const float* Wp = (chunk == 0) ? (Wa + lm * 128 + lk)
                                   : (Wc + lm * 256 + (chunk - 1) * 128 + lk);

    for (int k0 = 0; k0 < 128; k0 += 8) {
        float4 a = *(const float4*)(Ap + k0);
        float4 b = *(const float4*)(Wp + k0);
        As[lk + 0][lm] = a.x; As[lk + 1][lm] = a.y;
        As[lk + 2][lm] = a.z; As[lk + 3][lm] = a.w;
        Bs[lk + 0][lm] = b.x; Bs[lk + 1][lm] = b.y;
        Bs[lk + 2][lm] = b.z; Bs[lk + 3][lm] = b.w;
        __syncthreads();
        #pragma unroll
        for (int kk = 0; kk < 8; kk++) {
            float4 a0 = *(const float4*)&As[kk][ty * 4];
            float4 a1 = *(const float4*)&As[kk][64 + ty * 4];
            float4 b0 = *(const float4*)&Bs[kk][tx * 4];
            float4 b1 = *(const float4*)&Bs[kk][64 + tx * 4];
            float am[8] = {a0.x, a0.y, a0.z, a0.w, a1.x, a1.y, a1.z, a1.w};
            float bn[8] = {b0.x, b0.y, b0.z, b0.w, b1.x, b1.y, b1.z, b1.w};
            #pragma unroll
            for (int i = 0; i < 8; i++)
                #pragma unroll
                for (int j = 0; j < 8; j++)
                    acc[i][j] = fmaf(am[i], bn[j], acc[i][j]);
        }
        __syncthreads();
    }

    int cidx[8];
    #pragma unroll
    for (int j = 0; j < 8; j++)
        cidx[j] = (j < 4) ? (tx * 4 + j) : (64 + tx * 4 + (j - 4));

    if (chunk == 0) {
        // u_t row-reduction: sum_c va[c]*tanh(acc + ba[c])
        float vreg[8], breg[8];
        #pragma unroll
        for (int j = 0; j < 8; j++) { vreg[j] = va[cidx[j]]; breg[j] = ba[cidx[j]]; }
        #pragma unroll
        for (int i = 0; i < 8; i++) {
            float p = 0.f;
            #pragma unroll
            for (int j = 0; j < 8; j++)
                p += vreg[j] * tanhf(acc[i][j] + breg[j]);
            int m = (i < 4) ? (ty * 4 + i) : (64 + ty * 4 + (i - 4));
            red[m][tx] = p;
        }
        __syncthreads();
        if (tid < 128) {
            float s = 0.f;
            #pragma unroll
            for (int t = 0; t < 16; t++) s += red[tid][t];
            g_ut[row0 + tid] = s;
        }
    } else if (chunk == 1) {
        float breg[8];
        #pragma unroll
        for (int j = 0; j < 8; j++) breg[j] = bc[cidx[j]];
        #pragma unroll
        for (int i = 0; i < 8; i++) {
            int m = (i < 4) ? (ty * 4 + i) : (64 + ty * 4 + (i - 4));
            float* outp = g_X1b + (size_t)(row0 + m) * 128;
            float4 v0, v1;
            v0.x = acc[i][0] + breg[0]; v0.y = acc[i][1] + breg[1];
            v0.z = acc[i][2] + breg[2]; v0.w = acc[i][3] + breg[3];
            v1.x = acc[i][4] + breg[4]; v1.y = acc[i][5] + breg[5];
            v1.z = acc[i][6] + breg[6]; v1.w = acc[i][7] + breg[7];
            *(float4*)(outp + tx * 4)      = v0;
            *(float4*)(outp + 64 + tx * 4) = v1;
        }
    } else {
        #pragma unroll
        for (int i = 0; i < 8; i++) {
            int m = (i < 4) ? (ty * 4 + i) : (64 + ty * 4 + (i - 4));
            float* outp = g_X2 + (size_t)(row0 + m) * 128;
            float4 v0, v1;
            v0.x = acc[i][0]; v0.y = acc[i][1]; v0.z = acc[i][2]; v0.w = acc[i][3];
            v1.x = acc[i][4]; v1.y = acc[i][5]; v1.z = acc[i][6]; v1.w = acc[i][7];
            *(float4*)(outp + tx * 4)      = v0;
            *(float4*)(outp + 64 + tx * 4) = v1;
        }
    }
}

// ---------------- softmax over N=2048 per batch -----------------------------
// which==0: g_at = softmax(g_ut); which==1: g_prob = softmax(g_ut2)
// Device-global symbols are resolved INSIDE the kernel (never passed from host).
__global__ __launch_bounds__(256) void softmax_rows(int which)
{
    const float* u = (which == 0) ? g_ut : g_ut2;
    float* p       = (which == 0) ? g_at : g_prob;
    const int b = blockIdx.x;
    const float* ub = u + (size_t)b * NN;
    float* pb = p + (size_t)b * NN;
    const int tid = threadIdx.x;
    __shared__ float sm[256];

    float mx = -1e30f;
    for (int i = tid; i < NN; i += 256) mx = fmaxf(mx, ub[i]);
    sm[tid] = mx; __syncthreads();
    for (int s = 128; s > 0; s >>= 1) {
        if (tid < s) sm[tid] = fmaxf(sm[tid], sm[tid + s]);
        __syncthreads();
    }
    mx = sm[0]; __syncthreads();

    float sum = 0.f;
    for (int i = tid; i < NN; i += 256) {
        float e = __expf(ub[i] - mx);
        pb[i] = e;
        sum += e;
    }
    sm[tid] = sum; __syncthreads();
    for (int s = 128; s > 0; s >>= 1) {
        if (tid < s) sm[tid] += sm[tid + s];
        __syncthreads();
    }
    float inv = 1.f / sm[0];
    for (int i = tid; i < NN; i += 256) pb[i] *= inv;
}

// ---------------- u_t_2 = vc . tanh(X1b + a_t * X2) -------------------------
__global__ __launch_bounds__(256) void compute_ut2(const float* __restrict__ vc)
{
    const int row = blockIdx.x * 8 + (threadIdx.x >> 5);
    const int lane = threadIdx.x & 31;
    const float a = g_at[row];
    float4 v1 = ((const float4*)(g_X1b + (size_t)row * 128))[lane];
    float4 v2 = ((const float4*)(g_X2 + (size_t)row * 128))[lane];
    float4 vv = ((const float4*)vc)[lane];
    float s = vv.x * tanhf(v1.x + a * v2.x)
            + vv.y * tanhf(v1.y + a * v2.y)
            + vv.z * tanhf(v1.z + a * v2.z)
            + vv.w * tanhf(v1.w + a * v2.w);
    #pragma unroll
    for (int off = 16; off > 0; off >>= 1)
        s += __shfl_xor_sync(0xffffffffu, s, off);
    if (lane == 0) g_ut2[row] = s;
}

// ---------------- h_i = sum_n prob * proj ----------------------------------
__global__ __launch_bounds__(256) void reduce_hi()
{
    const int b = blockIdx.x;
    const int e = threadIdx.x & 127;
    const int half = threadIdx.x >> 7;
    float s = 0.f;
    const float* pb = g_prob + (size_t)b * NN;
    const float* prb = g_proj + (size_t)b * NN * 128;
    for (int n = half; n < NN; n += 2)
        s = fmaf(pb[n], prb[(size_t)n * 128 + e], s);
    __shared__ float sm[256];
    sm[threadIdx.x] = s; __syncthreads();
    if (half == 0) g_hi[b * 128 + e] = sm[e] + sm[128 + e];
}

// ---------------- final MLP: v = W2 . relu(W1 h + b1) + b2 ------------------
__global__ __launch_bounds__(128) void final_mlp(
    const float* __restrict__ W1, const float* __restrict__ b1,
    const float* __restrict__ W2, const float* __restrict__ b2,
    float* __restrict__ out)
{
    const int b = blockIdx.x;
    const int e = threadIdx.x;
    __shared__ float h[128];
    __shared__ float sm[128];
    h[e] = g_hi[b * 128 + e];
    __syncthreads();
    float s = b1[e];
    #pragma unroll 8
    for (int k = 0; k < 128; k++) s = fmaf(W1[e * 128 + k], h[k], s);
    sm[e] = fmaxf(s, 0.f) * W2[e];
    __syncthreads();
    for (int st = 64; st > 0; st >>= 1) {
        if (e < st) sm[e] += sm[e + st];
        __syncthreads();
    }
    if (e == 0) out[b] = sm[0] + b2[0];
}

// ---------------- launch ----------------------------------------------------
// Canonical indices: 0 instance,1 W_s,2 b_s,3 W_a,4 b_a,5 v_a,6 W_c,7 b_c,
//                    8 v_c,9 W1,10 b1,11 W2,12 b2
extern "C" void kernel_launch(void* const* d_in, const int* in_sizes, int n_in,
                              void* d_out, int out_size)
{
    // Candidate orderings: size signature + map[canonical] = position in d_in.
    static const int sigA[13] = {33554432,16384,128,16384,128,128,32768,128,128,16384,128,128,1};
    static const int mapA[13] = {0,1,2,3,4,5,6,7,8,9,10,11,12};                 // insertion
    static const int sigB[13] = {16384,128,16384,32768,16384,128,1,128,128,128,33554432,128,128};
    static const int mapB[13] = {10,4,9,2,7,11,3,8,12,0,5,1,6};                 // ASCII sort
    static const int sigC[13] = {128,1,128,128,128,33554432,128,128,16384,128,16384,32768,16384};
    static const int mapC[13] = {5,12,4,10,2,6,11,3,7,8,0,9,1};                 // lowercase sort

    const int* map = mapA;
    bool okA = true, okB = true, okC = true;
    for (int i = 0; i < 13 && i < n_in; i++) {
        if (in_sizes[i] != sigA[i]) okA = false;
        if (in_sizes[i] != sigB[i]) okB = false;
        if (in_sizes[i] != sigC[i]) okC = false;
    }
    int fb_map[13];
    if (okA)      map = mapA;
    else if (okB) map = mapB;
    else if (okC) map = mapC;
    else {
        // Fallback: unique sizes pinned; same-size groups assigned in order
        // of appearance per insertion order within each size class.
        int next16 = 0, next128 = 0;
        static const int ord16[3]  = {1, 3, 9};                 // W_s, W_a, W1
        static const int ord128[7] = {2, 4, 5, 7, 8, 10, 11};   // b_s,b_a,v_a,b_c,v_c,b1,W2
        for (int i = 0; i < 13; i++) fb_map[i] = i;
        for (int p = 0; p < 13 && p < n_in; p++) {
            int s = in_sizes[p];
            if (s == 33554432)      fb_map[0] = p;
            else if (s == 32768)    fb_map[6] = p;
            else if (s == 1)        fb_map[12] = p;
            else if (s == 16384)  { if (next16 < 3)  fb_map[ord16[next16++]]  = p; }
            else if (s == 128)    { if (next128 < 7) fb_map[ord128[next128++]] = p; }
        }
        map = fb_map;
    }

    const float* X  = (const float*)d_in[map[0]];
    const float* Ws = (const float*)d_in[map[1]];
    const float* bs = (const float*)d_in[map[2]];
    const float* Wa = (const float*)d_in[map[3]];
    const float* ba = (const float*)d_in[map[4]];
    const float* va = (const float*)d_in[map[5]];
    const float* Wc = (const float*)d_in[map[6]];
    const float* bc = (const float*)d_in[map[7]];
    const float* vc = (const float*)d_in[map[8]];
    const float* W1 = (const float*)d_in[map[9]];
    const float* b1 = (const float*)d_in[map[10]];
    const float* W2 = (const float*)d_in[map[11]];
    const float* b2 = (const float*)d_in[map[12]];
    float* out = (float*)d_out;

    gemm_proj<<<MT / 128, 256>>>(X, Ws, bs);
    gemm_attn<<<dim3(MT / 128, 3), 256>>>(Wa, ba, va, Wc, bc);
    softmax_rows<<<BB, 256>>>(0);
    compute_ut2<<<MT / 8, 256>>>(vc);
    softmax_rows<<<BB, 256>>>(1);
    reduce_hi<<<BB, 256>>>();
    final_mlp<<<BB, 128>>>(W1, b1, W2, b2, out);
}

// round 4
// speedup vs baseline: 1.0469x; 1.0469x over previous
#include <cuda_runtime.h>
#include <cuda_bf16.h>
#include <math.h>

// Problem constants
#define BB 128
#define NN 2048
#define EE 128
#define MT (BB * NN)   // 262144 total rows

// Packed fp32x2 FMA (Blackwell FFMA2 — only reachable via PTX)
#define PACKF2(p, lo, hi) \
    asm("mov.b64 %0, {%1, %2};" : "=l"(p) : "f"(lo), "f"(hi))
#define UNPACKF2(lo, hi, p) \
    asm("mov.b64 {%0, %1}, %2;" : "=f"(lo), "=f"(hi) : "l"(p))
#define FMA_F32X2(d, a, b, c) \
    asm("fma.rn.f32x2 %0, %1, %2, %3;" : "=l"(d) : "l"(a), "l"(b), "l"(c))

// ---------------- scratch (device globals; no allocation allowed) -----------
__device__ float g_proj[(size_t)MT * EE];   // [M,128]
__device__ float g_X1b [(size_t)MT * EE];   // W_c1*proj + b_c
__device__ float g_X2  [(size_t)MT * EE];   // W_c2*proj
__device__ float g_ut  [MT];
__device__ float g_at  [MT];
__device__ float g_ut2 [MT];
__device__ float g_prob[MT];
__device__ float g_hi  [BB * EE];

// ---------------- K1a: proj = X * Ws^T + bs  (tile 128x128, K=128) ----------
__global__ __launch_bounds__(256) void gemm_proj(
    const float* __restrict__ X,   // [M,128]
    const float* __restrict__ Ws,  // [128,128] row-major [e][s]
    const float* __restrict__ bs)  // [128]
{
    __shared__ float As[8][128];
    __shared__ float Bs[8][128];
    const int row0 = blockIdx.x * 128;
    const int tid = threadIdx.x;
    const int tx = tid & 15, ty = tid >> 4;
    const int lm = tid >> 1;            // 0..127
    const int lk = (tid & 1) * 4;       // 0 or 4

    unsigned long long accp[8][4];
    #pragma unroll
    for (int i = 0; i < 8; i++)
        #pragma unroll
        for (int j = 0; j < 4; j++) accp[i][j] = 0ull;

    const float* Xp = X + (size_t)(row0 + lm) * 128 + lk;
    const float* Wp = Ws + lm * 128 + lk;

    for (int k0 = 0; k0 < 128; k0 += 8) {
        float4 a = *(const float4*)(Xp + k0);
        float4 b = *(const float4*)(Wp + k0);
        As[lk + 0][lm] = a.x; As[lk + 1][lm] = a.y;
        As[lk + 2][lm] = a.z; As[lk + 3][lm] = a.w;
        Bs[lk + 0][lm] = b.x; Bs[lk + 1][lm] = b.y;
        Bs[lk + 2][lm] = b.z; Bs[lk + 3][lm] = b.w;
        __syncthreads();
        #pragma unroll
        for (int kk = 0; kk < 8; kk++) {
            float4 a0 = *(const float4*)&As[kk][ty * 4];
            float4 a1 = *(const float4*)&As[kk][64 + ty * 4];
            float4 b0 = *(const float4*)&Bs[kk][tx * 4];
            float4 b1 = *(const float4*)&Bs[kk][64 + tx * 4];
            float am[8] = {a0.x, a0.y, a0.z, a0.w, a1.x, a1.y, a1.z, a1.w};
            unsigned long long bp[4];
            PACKF2(bp[0], b0.x, b0.y); PACKF2(bp[1], b0.z, b0.w);
            PACKF2(bp[2], b1.x, b1.y); PACKF2(bp[3], b1.z, b1.w);
            #pragma unroll
            for (int i = 0; i < 8; i++) {
                unsigned long long ad;
                PACKF2(ad, am[i], am[i]);
                #pragma unroll
                for (int j = 0; j < 4; j++)
                    FMA_F32X2(accp[i][j], ad, bp[j], accp[i][j]);
            }
        }
        __syncthreads();
    }

    float breg[8];
    #pragma unroll
    for (int j = 0; j < 8; j++) {
        int c = (j < 4) ? (tx * 4 + j) : (64 + tx * 4 + (j - 4));
        breg[j] = bs[c];
    }
    #pragma unroll
    for (int i = 0; i < 8; i++) {
        int m = (i < 4) ? (ty * 4 + i) : (64 + ty * 4 + (i - 4));
        float acc[8];
        UNPACKF2(acc[0], acc[1], accp[i][0]);
        UNPACKF2(acc[2], acc[3], accp[i][1]);
        UNPACKF2(acc[4], acc[5], accp[i][2]);
        UNPACKF2(acc[6], acc[7], accp[i][3]);
        float* outp = g_proj + (size_t)(row0 + m) * 128;
        float4 v0, v1;
        v0.x = acc[0] + breg[0]; v0.y = acc[1] + breg[1];
        v0.z = acc[2] + breg[2]; v0.w = acc[3] + breg[3];
        v1.x = acc[4] + breg[4]; v1.y = acc[5] + breg[5];
        v1.z = acc[6] + breg[6]; v1.w = acc[7] + breg[7];
        *(float4*)(outp + tx * 4)      = v0;
        *(float4*)(outp + 64 + tx * 4) = v1;
    }
}

// ---------------- K1b: Y = proj * Wcat^T; 3 chunks (Wa / Wc1 / Wc2) --------
// 1D grid: bid = row_block*3 + chunk  (chunks for same rows launch adjacent
// so the shared A-tile read hits L2 instead of DRAM on 2 of 3 chunks)
__global__ __launch_bounds__(256) void gemm_attn(
    const float* __restrict__ Wa,   // [128][128]
    const float* __restrict__ ba,   // [128]
    const float* __restrict__ va,   // [128]
    const float* __restrict__ Wc,   // [128][256]
    const float* __restrict__ bc)   // [128]
{
    __shared__ float As[8][128];
    __shared__ float Bs[8][128];
    __shared__ float red[128][17];
    const int chunk = blockIdx.x % 3;       // 0: Wa, 1: Wc[:, :128], 2: Wc[:, 128:]
    const int row0 = (blockIdx.x / 3) * 128;
    const int tid = threadIdx.x;
    const int tx = tid & 15, ty = tid >> 4;
    const int lm = tid >> 1;
    const int lk = (tid & 1) * 4;

    unsigned long long accp[8][4];
    #pragma unroll
    for (int i = 0; i < 8; i++)
        #pragma unroll
        for (int j = 0; j < 4; j++) accp[i][j] = 0ull;

    const float* Ap = g_proj + (size_t)(row0 + lm) * 128 + lk;
    const float* Wp = (chunk == 0) ? (Wa + lm * 128 + lk)
                                   : (Wc + lm * 256 + (chunk - 1) * 128 + lk);

    for (int k0 = 0; k0 < 128; k0 += 8) {
        float4 a = *(const float4*)(Ap + k0);
        float4 b = *(const float4*)(Wp + k0);
        As[lk + 0][lm] = a.x; As[lk + 1][lm] = a.y;
        As[lk + 2][lm] = a.z; As[lk + 3][lm] = a.w;
        Bs[lk + 0][lm] = b.x; Bs[lk + 1][lm] = b.y;
        Bs[lk + 2][lm] = b.z; Bs[lk + 3][lm] = b.w;
        __syncthreads();
        #pragma unroll
        for (int kk = 0; kk < 8; kk++) {
            float4 a0 = *(const float4*)&As[kk][ty * 4];
            float4 a1 = *(const float4*)&As[kk][64 + ty * 4];
            float4 b0 = *(const float4*)&Bs[kk][tx * 4];
            float4 b1 = *(const float4*)&Bs[kk][64 + tx * 4];
            float am[8] = {a0.x, a0.y, a0.z, a0.w, a1.x, a1.y, a1.z, a1.w};
            unsigned long long bp[4];
            PACKF2(bp[0], b0.x, b0.y); PACKF2(bp[1], b0.z, b0.w);
            PACKF2(bp[2], b1.x, b1.y); PACKF2(bp[3], b1.z, b1.w);
            #pragma unroll
            for (int i = 0; i < 8; i++) {
                unsigned long long ad;
                PACKF2(ad, am[i], am[i]);
                #pragma unroll
                for (int j = 0; j < 4; j++)
                    FMA_F32X2(accp[i][j], ad, bp[j], accp[i][j]);
            }
        }
        __syncthreads();
    }

    int cidx[8];
    #pragma unroll
    for (int j = 0; j < 8; j++)
        cidx[j] = (j < 4) ? (tx * 4 + j) : (64 + tx * 4 + (j - 4));

    if (chunk == 0) {
        // u_t row-reduction: sum_c va[c]*tanh(acc + ba[c])
        float vreg[8], breg[8];
        #pragma unroll
        for (int j = 0; j < 8; j++) { vreg[j] = va[cidx[j]]; breg[j] = ba[cidx[j]]; }
        #pragma unroll
        for (int i = 0; i < 8; i++) {
            float acc[8];
            UNPACKF2(acc[0], acc[1], accp[i][0]);
            UNPACKF2(acc[2], acc[3], accp[i][1]);
            UNPACKF2(acc[4], acc[5], accp[i][2]);
            UNPACKF2(acc[6], acc[7], accp[i][3]);
            float p = 0.f;
            #pragma unroll
            for (int j = 0; j < 8; j++)
                p += vreg[j] * tanhf(acc[j] + breg[j]);
            int m = (i < 4) ? (ty * 4 + i) : (64 + ty * 4 + (i - 4));
            red[m][tx] = p;
        }
        __syncthreads();
        if (tid < 128) {
            float s = 0.f;
            #pragma unroll
            for (int t = 0; t < 16; t++) s += red[tid][t];
            g_ut[row0 + tid] = s;
        }
    } else if (chunk == 1) {
        float breg[8];
        #pragma unroll
        for (int j = 0; j < 8; j++) breg[j] = bc[cidx[j]];
        #pragma unroll
        for (int i = 0; i < 8; i++) {
            float acc[8];
            UNPACKF2(acc[0], acc[1], accp[i][0]);
            UNPACKF2(acc[2], acc[3], accp[i][1]);
            UNPACKF2(acc[4], acc[5], accp[i][2]);
            UNPACKF2(acc[6], acc[7], accp[i][3]);
            int m = (i < 4) ? (ty * 4 + i) : (64 + ty * 4 + (i - 4));
            float* outp = g_X1b + (size_t)(row0 + m) * 128;
            float4 v0, v1;
            v0.x = acc[0] + breg[0]; v0.y = acc[1] + breg[1];
            v0.z = acc[2] + breg[2]; v0.w = acc[3] + breg[3];
            v1.x = acc[4] + breg[4]; v1.y = acc[5] + breg[5];
            v1.z = acc[6] + breg[6]; v1.w = acc[7] + breg[7];
            *(float4*)(outp + tx * 4)      = v0;
            *(float4*)(outp + 64 + tx * 4) = v1;
        }
    } else {
        #pragma unroll
        for (int i = 0; i < 8; i++) {
            float acc[8];
            UNPACKF2(acc[0], acc[1], accp[i][0]);
            UNPACKF2(acc[2], acc[3], accp[i][1]);
            UNPACKF2(acc[4], acc[5], accp[i][2]);
            UNPACKF2(acc[6], acc[7], accp[i][3]);
            int m = (i < 4) ? (ty * 4 + i) : (64 + ty * 4 + (i - 4));
            float* outp = g_X2 + (size_t)(row0 + m) * 128;
            float4 v0, v1;
            v0.x = acc[0]; v0.y = acc[1]; v0.z = acc[2]; v0.w = acc[3];
            v1.x = acc[4]; v1.y = acc[5]; v1.z = acc[6]; v1.w = acc[7];
            *(float4*)(outp + tx * 4)      = v0;
            *(float4*)(outp + 64 + tx * 4) = v1;
        }
    }
}

// ---------------- softmax over N=2048 per batch -----------------------------
// which==0: g_at = softmax(g_ut); which==1: g_prob = softmax(g_ut2)
__global__ __launch_bounds__(256) void softmax_rows(int which)
{
    const float* u = (which == 0) ? g_ut : g_ut2;
    float* p       = (which == 0) ? g_at : g_prob;
    const int b = blockIdx.x;
    const float* ub = u + (size_t)b * NN;
    float* pb = p + (size_t)b * NN;
    const int tid = threadIdx.x;
    __shared__ float sm[256];

    float mx = -1e30f;
    for (int i = tid; i < NN; i += 256) mx = fmaxf(mx, ub[i]);
    sm[tid] = mx; __syncthreads();
    for (int s = 128; s > 0; s >>= 1) {
        if (tid < s) sm[tid] = fmaxf(sm[tid], sm[tid + s]);
        __syncthreads();
    }
    mx = sm[0]; __syncthreads();

    float sum = 0.f;
    for (int i = tid; i < NN; i += 256) {
        float e = __expf(ub[i] - mx);
        pb[i] = e;
        sum += e;
    }
    sm[tid] = sum; __syncthreads();
    for (int s = 128; s > 0; s >>= 1) {
        if (tid < s) sm[tid] += sm[tid + s];
        __syncthreads();
    }
    float inv = 1.f / sm[0];
    for (int i = tid; i < NN; i += 256) pb[i] *= inv;
}

// ---------------- u_t_2 = vc . tanh(X1b + a_t * X2) -------------------------
__global__ __launch_bounds__(256) void compute_ut2(const float* __restrict__ vc)
{
    const int row = blockIdx.x * 8 + (threadIdx.x >> 5);
    const int lane = threadIdx.x & 31;
    const float a = g_at[row];
    float4 v1 = ((const float4*)(g_X1b + (size_t)row * 128))[lane];
    float4 v2 = ((const float4*)(g_X2 + (size_t)row * 128))[lane];
    float4 vv = ((const float4*)vc)[lane];
    float s = vv.x * tanhf(v1.x + a * v2.x)
            + vv.y * tanhf(v1.y + a * v2.y)
            + vv.z * tanhf(v1.z + a * v2.z)
            + vv.w * tanhf(v1.w + a * v2.w);
    #pragma unroll
    for (int off = 16; off > 0; off >>= 1)
        s += __shfl_xor_sync(0xffffffffu, s, off);
    if (lane == 0) g_ut2[row] = s;
}

// ---------------- h_i = sum_n prob * proj ----------------------------------
__global__ __launch_bounds__(256) void reduce_hi()
{
    const int b = blockIdx.x;
    const int e = threadIdx.x & 127;
    const int half = threadIdx.x >> 7;
    float s = 0.f;
    const float* pb = g_prob + (size_t)b * NN;
    const float* prb = g_proj + (size_t)b * NN * 128;
    for (int n = half; n < NN; n += 2)
        s = fmaf(pb[n], prb[(size_t)n * 128 + e], s);
    __shared__ float sm[256];
    sm[threadIdx.x] = s; __syncthreads();
    if (half == 0) g_hi[b * 128 + e] = sm[e] + sm[128 + e];
}

// ---------------- final MLP: v = W2 . relu(W1 h + b1) + b2 ------------------
__global__ __launch_bounds__(128) void final_mlp(
    const float* __restrict__ W1, const float* __restrict__ b1,
    const float* __restrict__ W2, const float* __restrict__ b2,
    float* __restrict__ out)
{
    const int b = blockIdx.x;
    const int e = threadIdx.x;
    __shared__ float h[128];
    __shared__ float sm[128];
    h[e] = g_hi[b * 128 + e];
    __syncthreads();
    float s = b1[e];
    #pragma unroll 8
    for (int k = 0; k < 128; k++) s = fmaf(W1[e * 128 + k], h[k], s);
    sm[e] = fmaxf(s, 0.f) * W2[e];
    __syncthreads();
    for (int st = 64; st > 0; st >>= 1) {
        if (e < st) sm[e] += sm[e + st];
        __syncthreads();
    }
    if (e == 0) out[b] = sm[0] + b2[0];
}

// ---------------- launch ----------------------------------------------------
// Canonical indices: 0 instance,1 W_s,2 b_s,3 W_a,4 b_a,5 v_a,6 W_c,7 b_c,
//                    8 v_c,9 W1,10 b1,11 W2,12 b2
extern "C" void kernel_launch(void* const* d_in, const int* in_sizes, int n_in,
                              void* d_out, int out_size)
{
    // Candidate orderings: size signature + map[canonical] = position in d_in.
    static const int sigA[13] = {33554432,16384,128,16384,128,128,32768,128,128,16384,128,128,1};
    static const int mapA[13] = {0,1,2,3,4,5,6,7,8,9,10,11,12};                 // insertion
    static const int sigB[13] = {16384,128,16384,32768,16384,128,1,128,128,128,33554432,128,128};
    static const int mapB[13] = {10,4,9,2,7,11,3,8,12,0,5,1,6};                 // ASCII sort
    static const int sigC[13] = {128,1,128,128,128,33554432,128,128,16384,128,16384,32768,16384};
    static const int mapC[13] = {5,12,4,10,2,6,11,3,7,8,0,9,1};                 // lowercase sort

    const int* map = mapA;
    bool okA = true, okB = true, okC = true;
    for (int i = 0; i < 13 && i < n_in; i++) {
        if (in_sizes[i] != sigA[i]) okA = false;
        if (in_sizes[i] != sigB[i]) okB = false;
        if (in_sizes[i] != sigC[i]) okC = false;
    }
    int fb_map[13];
    if (okA)      map = mapA;
    else if (okB) map = mapB;
    else if (okC) map = mapC;
    else {
        int next16 = 0, next128 = 0;
        static const int ord16[3]  = {1, 3, 9};                 // W_s, W_a, W1
        static const int ord128[7] = {2, 4, 5, 7, 8, 10, 11};   // b_s,b_a,v_a,b_c,v_c,b1,W2
        for (int i = 0; i < 13; i++) fb_map[i] = i;
        for (int p = 0; p < 13 && p < n_in; p++) {
            int s = in_sizes[p];
            if (s == 33554432)      fb_map[0] = p;
            else if (s == 32768)    fb_map[6] = p;
            else if (s == 1)        fb_map[12] = p;
            else if (s == 16384)  { if (next16 < 3)  fb_map[ord16[next16++]]  = p; }
            else if (s == 128)    { if (next128 < 7) fb_map[ord128[next128++]] = p; }
        }
        map = fb_map;
    }

    const float* X  = (const float*)d_in[map[0]];
    const float* Ws = (const float*)d_in[map[1]];
    const float* bs = (const float*)d_in[map[2]];
    const float* Wa = (const float*)d_in[map[3]];
    const float* ba = (const float*)d_in[map[4]];
    const float* va = (const float*)d_in[map[5]];
    const float* Wc = (const float*)d_in[map[6]];
    const float* bc = (const float*)d_in[map[7]];
    const float* vc = (const float*)d_in[map[8]];
    const float* W1 = (const float*)d_in[map[9]];
    const float* b1 = (const float*)d_in[map[10]];
    const float* W2 = (const float*)d_in[map[11]];
    const float* b2 = (const float*)d_in[map[12]];
    float* out = (float*)d_out;

    gemm_proj<<<MT / 128, 256>>>(X, Ws, bs);
    gemm_attn<<<(MT / 128) * 3, 256>>>(Wa, ba, va, Wc, bc);
    softmax_rows<<<BB, 256>>>(0);
    compute_ut2<<<MT / 8, 256>>>(vc);
    softmax_rows<<<BB, 256>>>(1);
    reduce_hi<<<BB, 256>>>();
    final_mlp<<<BB, 128>>>(W1, b1, W2, b2, out);
}

// round 5
// speedup vs baseline: 1.5509x; 1.4814x over previous
#include <cuda_runtime.h>
#include <cuda_bf16.h>
#include <math.h>

// Problem constants
#define BB 128
#define NN 2048
#define EE 128
#define MT (BB * NN)   // 262144 total rows

// ---------------- scratch (device globals; no allocation allowed) -----------
__device__ float g_proj[(size_t)MT * EE];   // [M,128]
__device__ float g_X1b [(size_t)MT * EE];   // W_c1*proj + b_c
__device__ float g_X2  [(size_t)MT * EE];   // W_c2*proj
__device__ float g_ut  [MT];
__device__ float g_at  [MT];
__device__ float g_ut2 [MT];
__device__ float g_prob[MT];
__device__ float g_hi  [BB * EE];

// Packed weight fragments (bf16 hi/lo, per-lane mma fragment order).
// Entry (nb*8+kt)*32+lane = {hi(k,k+1), hi(k+8,k+9), lo(k,k+1), lo(k+8,k+9)}
// with n = 8*nb+gid, k = 16*kt+2*tig.
__device__ uint4 g_WsP[16 * 8 * 32];        // Ws  [128 x 128]  -> 16 n-blocks
__device__ uint4 g_WtP[48 * 8 * 32];        // [Wa; Wc1; Wc2] [384 x 128] -> 48

__device__ __forceinline__ void split2(float x0, float x1,
                                       unsigned &hi, unsigned &lo) {
    __nv_bfloat16 h0 = __float2bfloat16_rn(x0);
    __nv_bfloat16 h1 = __float2bfloat16_rn(x1);
    float r0 = x0 - __bfloat162float(h0);
    float r1 = x1 - __bfloat162float(h1);
    __nv_bfloat162 hh; hh.x = h0; hh.y = h1;
    __nv_bfloat162 ll; ll.x = __float2bfloat16_rn(r0);
                       ll.y = __float2bfloat16_rn(r1);
    hi = *reinterpret_cast<unsigned*>(&hh);
    lo = *reinterpret_cast<unsigned*>(&ll);
}

#define MMA16816(d, a, b0_, b1_) \
  asm volatile("mma.sync.aligned.m16n8k16.row.col.f32.bf16.bf16.f32 " \
    "{%0,%1,%2,%3}, {%4,%5,%6,%7}, {%8,%9}, {%0,%1,%2,%3};" \
    : "+f"(d[0]), "+f"(d[1]), "+f"(d[2]), "+f"(d[3]) \
    : "r"(a[0]), "r"(a[1]), "r"(a[2]), "r"(a[3]), "r"(b0_), "r"(b1_))

// ---------------- weight prep: fp32 -> bf16 hi/lo fragment-packed -----------
__global__ __launch_bounds__(256) void prep_weights(
    const float* __restrict__ Ws, const float* __restrict__ Wa,
    const float* __restrict__ Wc)
{
    int i = blockIdx.x * 256 + threadIdx.x;     // 0..65535 (one uint each)
    int stage = (i >= 16384) ? 1 : 0;
    int rem = stage ? (i - 16384) : i;
    int j    = rem & 3;
    int lane = (rem >> 2) & 31;
    int kt   = (rem >> 7) & 7;
    int nb   = rem >> 10;
    int gid = lane >> 2, tig = lane & 3;
    int n = nb * 8 + gid;
    int k = kt * 16 + ((j & 1) ? 8 : 0) + 2 * tig;
    float w0, w1;
    if (!stage)        { w0 = Ws[n * 128 + k];            w1 = Ws[n * 128 + k + 1]; }
    else if (n < 128)  { w0 = Wa[n * 128 + k];            w1 = Wa[n * 128 + k + 1]; }
    else if (n < 256)  { w0 = Wc[(n - 128) * 256 + k];    w1 = Wc[(n - 128) * 256 + k + 1]; }
    else               { w0 = Wc[(n - 256) * 256 + 128 + k];
                         w1 = Wc[(n - 256) * 256 + 128 + k + 1]; }
    unsigned hi, lo;
    split2(w0, w1, hi, lo);
    unsigned* dst = stage ? (unsigned*)g_WtP : (unsigned*)g_WsP;
    dst[((nb * 8 + kt) * 32 + lane) * 4 + j] = (j < 2) ? hi : lo;
}

// ---------------- fused: X -> proj -> {u_t, X1b, X2} (all tensor-core) ------
// Per warp: 16 rows. Split-bf16 mma, D-frag -> A-frag register reuse.
__global__ __launch_bounds__(256) void fused_gemms(
    const float* __restrict__ X,  const float* __restrict__ bs,
    const float* __restrict__ ba, const float* __restrict__ va,
    const float* __restrict__ bc)
{
    const int wid = threadIdx.x >> 5, lane = threadIdx.x & 31;
    const int gid = lane >> 2, tig = lane & 3;
    const size_t r0 = (size_t)blockIdx.x * 128 + wid * 16 + gid;
    const size_t r1 = r0 + 8;

    // ---- stage A: proj = X * Ws^T  (16 n-blocks of 8 cols) ----
    float acc[16][4];
    #pragma unroll
    for (int b = 0; b < 16; b++)
        acc[b][0] = acc[b][1] = acc[b][2] = acc[b][3] = 0.f;

    const float* x0p = X + r0 * 128;
    const float* x1p = X + r1 * 128;

    #pragma unroll
    for (int kt = 0; kt < 8; kt++) {
        const int k0 = kt * 16;
        float2 xa = *(const float2*)(x0p + k0 + 2 * tig);
        float2 xb = *(const float2*)(x1p + k0 + 2 * tig);
        float2 xc = *(const float2*)(x0p + k0 + 8 + 2 * tig);
        float2 xd = *(const float2*)(x1p + k0 + 8 + 2 * tig);
        unsigned ah[4], al[4];
        split2(xa.x, xa.y, ah[0], al[0]);
        split2(xb.x, xb.y, ah[1], al[1]);
        split2(xc.x, xc.y, ah[2], al[2]);
        split2(xd.x, xd.y, ah[3], al[3]);
        #pragma unroll
        for (int b = 0; b < 16; b++) {
            uint4 q = g_WsP[(b * 8 + kt) * 32 + lane];
            MMA16816(acc[b], ah, q.x, q.y);   // hi*hi
            MMA16816(acc[b], ah, q.z, q.w);   // hi*lo
            MMA16816(acc[b], al, q.x, q.y);   // lo*hi
        }
    }

    // bias + store proj + convert D-frags into A'-frags (bf16 hi/lo)
    unsigned aph[8][4], apl[8][4];
    #pragma unroll
    for (int b = 0; b < 16; b++) {
        const int c0 = 8 * b + 2 * tig;
        float b0v = bs[c0], b1v = bs[c0 + 1];
        acc[b][0] += b0v; acc[b][1] += b1v;
        acc[b][2] += b0v; acc[b][3] += b1v;
        *(float2*)(g_proj + r0 * 128 + c0) = make_float2(acc[b][0], acc[b][1]);
        *(float2*)(g_proj + r1 * 128 + c0) = make_float2(acc[b][2], acc[b][3]);
    }
    #pragma unroll
    for (int kt = 0; kt < 8; kt++) {
        split2(acc[2*kt  ][0], acc[2*kt  ][1], aph[kt][0], apl[kt][0]);
        split2(acc[2*kt  ][2], acc[2*kt  ][3], aph[kt][1], apl[kt][1]);
        split2(acc[2*kt+1][0], acc[2*kt+1][1], aph[kt][2], apl[kt][2]);
        split2(acc[2*kt+1][2], acc[2*kt+1][3], aph[kt][3], apl[kt][3]);
    }

    // ---- stage B: Y = proj * [Wa; Wc1; Wc2]^T  (48 n-blocks, 6 chunks) ----
    float ut0 = 0.f, ut1 = 0.f;
    for (int chunk = 0; chunk < 6; chunk++) {
        float d[8][4];
        #pragma unroll
        for (int b = 0; b < 8; b++)
            d[b][0] = d[b][1] = d[b][2] = d[b][3] = 0.f;
        #pragma unroll
        for (int kt = 0; kt < 8; kt++) {
            #pragma unroll
            for (int b = 0; b < 8; b++) {
                const int nb = chunk * 8 + b;
                uint4 q = g_WtP[(nb * 8 + kt) * 32 + lane];
                MMA16816(d[b], aph[kt], q.x, q.y);
                MMA16816(d[b], aph[kt], q.z, q.w);
                MMA16816(d[b], apl[kt], q.x, q.y);
            }
        }
        if (chunk < 2) {
            // Wa part: u_t += va .* tanh(. + ba)
            #pragma unroll
            for (int b = 0; b < 8; b++) {
                const int c0 = chunk * 64 + 8 * b + 2 * tig;
                float ba0 = ba[c0], ba1 = ba[c0 + 1];
                float va0 = va[c0], va1 = va[c0 + 1];
                ut0 += va0 * tanhf(d[b][0] + ba0) + va1 * tanhf(d[b][1] + ba1);
                ut1 += va0 * tanhf(d[b][2] + ba0) + va1 * tanhf(d[b][3] + ba1);
            }
        } else if (chunk < 4) {
            #pragma unroll
            for (int b = 0; b < 8; b++) {
                const int c0 = (chunk - 2) * 64 + 8 * b + 2 * tig;
                float bc0 = bc[c0], bc1 = bc[c0 + 1];
                *(float2*)(g_X1b + r0 * 128 + c0) = make_float2(d[b][0] + bc0, d[b][1] + bc1);
                *(float2*)(g_X1b + r1 * 128 + c0) = make_float2(d[b][2] + bc0, d[b][3] + bc1);
            }
        } else {
            #pragma unroll
            for (int b = 0; b < 8; b++) {
                const int c0 = (chunk - 4) * 64 + 8 * b + 2 * tig;
                *(float2*)(g_X2 + r0 * 128 + c0) = make_float2(d[b][0], d[b][1]);
                *(float2*)(g_X2 + r1 * 128 + c0) = make_float2(d[b][2], d[b][3]);
            }
        }
    }
    // reduce u_t over the 4 lanes of each row group (tig axis)
    ut0 += __shfl_xor_sync(0xffffffffu, ut0, 1);
    ut0 += __shfl_xor_sync(0xffffffffu, ut0, 2);
    ut1 += __shfl_xor_sync(0xffffffffu, ut1, 1);
    ut1 += __shfl_xor_sync(0xffffffffu, ut1, 2);
    if (tig == 0) { g_ut[r0] = ut0; g_ut[r1] = ut1; }
}

// ---------------- softmax over N=2048 per batch -----------------------------
__global__ __launch_bounds__(256) void softmax_rows(int which)
{
    const float* u = (which == 0) ? g_ut : g_ut2;
    float* p       = (which == 0) ? g_at : g_prob;
    const int b = blockIdx.x;
    const float* ub = u + (size_t)b * NN;
    float* pb = p + (size_t)b * NN;
    const int tid = threadIdx.x;
    __shared__ float sm[256];

    float mx = -1e30f;
    for (int i = tid; i < NN; i += 256) mx = fmaxf(mx, ub[i]);
    sm[tid] = mx; __syncthreads();
    for (int s = 128; s > 0; s >>= 1) {
        if (tid < s) sm[tid] = fmaxf(sm[tid], sm[tid + s]);
        __syncthreads();
    }
    mx = sm[0]; __syncthreads();

    float sum = 0.f;
    for (int i = tid; i < NN; i += 256) {
        float e = __expf(ub[i] - mx);
        pb[i] = e;
        sum += e;
    }
    sm[tid] = sum; __syncthreads();
    for (int s = 128; s > 0; s >>= 1) {
        if (tid < s) sm[tid] += sm[tid + s];
        __syncthreads();
    }
    float inv = 1.f / sm[0];
    for (int i = tid; i < NN; i += 256) pb[i] *= inv;
}

// ---------------- u_t_2 = vc . tanh(X1b + a_t * X2) -------------------------
__global__ __launch_bounds__(256) void compute_ut2(const float* __restrict__ vc)
{
    const int row = blockIdx.x * 8 + (threadIdx.x >> 5);
    const int lane = threadIdx.x & 31;
    const float a = g_at[row];
    float4 v1 = ((const float4*)(g_X1b + (size_t)row * 128))[lane];
    float4 v2 = ((const float4*)(g_X2 + (size_t)row * 128))[lane];
    float4 vv = ((const float4*)vc)[lane];
    float s = vv.x * tanhf(v1.x + a * v2.x)
            + vv.y * tanhf(v1.y + a * v2.y)
            + vv.z * tanhf(v1.z + a * v2.z)
            + vv.w * tanhf(v1.w + a * v2.w);
    #pragma unroll
    for (int off = 16; off > 0; off >>= 1)
        s += __shfl_xor_sync(0xffffffffu, s, off);
    if (lane == 0) g_ut2[row] = s;
}

// ---------------- h_i = sum_n prob * proj ----------------------------------
__global__ __launch_bounds__(256) void reduce_hi()
{
    const int b = blockIdx.x;
    const int e = threadIdx.x & 127;
    const int half = threadIdx.x >> 7;
    float s = 0.f;
    const float* pb = g_prob + (size_t)b * NN;
    const float* prb = g_proj + (size_t)b * NN * 128;
    for (int n = half; n < NN; n += 2)
        s = fmaf(pb[n], prb[(size_t)n * 128 + e], s);
    __shared__ float sm[256];
    sm[threadIdx.x] = s; __syncthreads();
    if (half == 0) g_hi[b * 128 + e] = sm[e] + sm[128 + e];
}

// ---------------- final MLP: v = W2 . relu(W1 h + b1) + b2 ------------------
__global__ __launch_bounds__(128) void final_mlp(
    const float* __restrict__ W1, const float* __restrict__ b1,
    const float* __restrict__ W2, const float* __restrict__ b2,
    float* __restrict__ out)
{
    const int b = blockIdx.x;
    const int e = threadIdx.x;
    __shared__ float h[128];
    __shared__ float sm[128];
    h[e] = g_hi[b * 128 + e];
    __syncthreads();
    float s = b1[e];
    #pragma unroll 8
    for (int k = 0; k < 128; k++) s = fmaf(W1[e * 128 + k], h[k], s);
    sm[e] = fmaxf(s, 0.f) * W2[e];
    __syncthreads();
    for (int st = 64; st > 0; st >>= 1) {
        if (e < st) sm[e] += sm[e + st];
        __syncthreads();
    }
    if (e == 0) out[b] = sm[0] + b2[0];
}

// ---------------- launch ----------------------------------------------------
// Canonical indices: 0 instance,1 W_s,2 b_s,3 W_a,4 b_a,5 v_a,6 W_c,7 b_c,
//                    8 v_c,9 W1,10 b1,11 W2,12 b2
extern "C" void kernel_launch(void* const* d_in, const int* in_sizes, int n_in,
                              void* d_out, int out_size)
{
    static const int sigA[13] = {33554432,16384,128,16384,128,128,32768,128,128,16384,128,128,1};
    static const int mapA[13] = {0,1,2,3,4,5,6,7,8,9,10,11,12};                 // insertion
    static const int sigB[13] = {16384,128,16384,32768,16384,128,1,128,128,128,33554432,128,128};
    static const int mapB[13] = {10,4,9,2,7,11,3,8,12,0,5,1,6};                 // ASCII sort
    static const int sigC[13] = {128,1,128,128,128,33554432,128,128,16384,128,16384,32768,16384};
    static const int mapC[13] = {5,12,4,10,2,6,11,3,7,8,0,9,1};                 // lowercase sort

    const int* map = mapA;
    bool okA = true, okB = true, okC = true;
    for (int i = 0; i < 13 && i < n_in; i++) {
        if (in_sizes[i] != sigA[i]) okA = false;
        if (in_sizes[i] != sigB[i]) okB = false;
        if (in_sizes[i] != sigC[i]) okC = false;
    }
    int fb_map[13];
    if (okA)      map = mapA;
    else if (okB) map = mapB;
    else if (okC) map = mapC;
    else {
        int next16 = 0, next128 = 0;
        static const int ord16[3]  = {1, 3, 9};
        static const int ord128[7] = {2, 4, 5, 7, 8, 10, 11};
        for (int i = 0; i < 13; i++) fb_map[i] = i;
        for (int p = 0; p < 13 && p < n_in; p++) {
            int s = in_sizes[p];
            if (s == 33554432)      fb_map[0] = p;
            else if (s == 32768)    fb_map[6] = p;
            else if (s == 1)        fb_map[12] = p;
            else if (s == 16384)  { if (next16 < 3)  fb_map[ord16[next16++]]  = p; }
            else if (s == 128)    { if (next128 < 7) fb_map[ord128[next128++]] = p; }
        }
        map = fb_map;
    }

    const float* X  = (const float*)d_in[map[0]];
    const float* Ws = (const float*)d_in[map[1]];
    const float* bs = (const float*)d_in[map[2]];
    const float* Wa = (const float*)d_in[map[3]];
    const float* ba = (const float*)d_in[map[4]];
    const float* va = (const float*)d_in[map[5]];
    const float* Wc = (const float*)d_in[map[6]];
    const float* bc = (const float*)d_in[map[7]];
    const float* vc = (const float*)d_in[map[8]];
    const float* W1 = (const float*)d_in[map[9]];
    const float* b1 = (const float*)d_in[map[10]];
    const float* W2 = (const float*)d_in[map[11]];
    const float* b2 = (const float*)d_in[map[12]];
    float* out = (float*)d_out;

    prep_weights<<<256, 256>>>(Ws, Wa, Wc);
    fused_gemms<<<MT / 128, 256>>>(X, bs, ba, va, bc);
    softmax_rows<<<BB, 256>>>(0);
    compute_ut2<<<MT / 8, 256>>>(vc);
    softmax_rows<<<BB, 256>>>(1);
    reduce_hi<<<BB, 256>>>();
    final_mlp<<<BB, 128>>>(W1, b1, W2, b2, out);
}

// round 11
// speedup vs baseline: 1.9434x; 1.2530x over previous
#include <cuda_runtime.h>
#include <cuda_bf16.h>
#include <math.h>
#include <stdint.h>

// Problem constants
#define BB 128
#define NN 2048
#define EE 128
#define MT (BB * NN)   // 262144 total rows
#define NGROUPS (MT / 16)  // 16384 16-row groups

// ---------------- scratch (device globals; no allocation allowed) -----------
__device__ float g_proj[(size_t)MT * EE];   // [M,128]
__device__ float g_X1b [(size_t)MT * EE];   // W_c1*proj + b_c
__device__ float g_X2  [(size_t)MT * EE];   // W_c2*proj
__device__ float g_ut  [MT];
__device__ float g_at  [MT];
__device__ float g_ut2 [MT];
__device__ float g_prob[MT];
__device__ float g_hi  [BB * EE];

// Packed weight fragments (bf16 hi/lo, per-lane mma fragment order).
// Entry (nb*8+kt)*32+lane = {hi(k,k+1), hi(k+8,k+9), lo(k,k+1), lo(k+8,k+9)}
// with n = 8*nb+gid, k = 16*kt+2*tig.
__device__ uint4 g_WsP[16 * 8 * 32];        // Ws  [128 x 128]  -> 16 n-blocks
__device__ uint4 g_WtP[48 * 8 * 32];        // [Wa; Wc1; Wc2] [384 x 128] -> 48

__device__ __forceinline__ void split2(float x0, float x1,
                                       unsigned &hi, unsigned &lo) {
    __nv_bfloat16 h0 = __float2bfloat16_rn(x0);
    __nv_bfloat16 h1 = __float2bfloat16_rn(x1);
    float r0 = x0 - __bfloat162float(h0);
    float r1 = x1 - __bfloat162float(h1);
    __nv_bfloat162 hh; hh.x = h0; hh.y = h1;
    __nv_bfloat162 ll; ll.x = __float2bfloat16_rn(r0);
                       ll.y = __float2bfloat16_rn(r1);
    hi = *reinterpret_cast<unsigned*>(&hh);
    lo = *reinterpret_cast<unsigned*>(&ll);
}

#define MMA16816(d, a, b0_, b1_) \
  asm volatile("mma.sync.aligned.m16n8k16.row.col.f32.bf16.bf16.f32 " \
    "{%0,%1,%2,%3}, {%4,%5,%6,%7}, {%8,%9}, {%0,%1,%2,%3};" \
    : "+f"(d[0]), "+f"(d[1]), "+f"(d[2]), "+f"(d[3]) \
    : "r"(a[0]), "r"(a[1]), "r"(a[2]), "r"(a[3]), "r"(b0_), "r"(b1_))

// 12 MMAs over 4 independent accumulators (hi*Whi, hi*Wlo, lo*Whi),
// dependent distance 4 -> hides HMMA latency.
#define MMA_GROUP4(ACC, B0, AH, AL, Q0, Q1, Q2, Q3) do { \
    MMA16816(ACC[B0 + 0], AH, Q0.x, Q0.y); \
    MMA16816(ACC[B0 + 1], AH, Q1.x, Q1.y); \
    MMA16816(ACC[B0 + 2], AH, Q2.x, Q2.y); \
    MMA16816(ACC[B0 + 3], AH, Q3.x, Q3.y); \
    MMA16816(ACC[B0 + 0], AH, Q0.z, Q0.w); \
    MMA16816(ACC[B0 + 1], AH, Q1.z, Q1.w); \
    MMA16816(ACC[B0 + 2], AH, Q2.z, Q2.w); \
    MMA16816(ACC[B0 + 3], AH, Q3.z, Q3.w); \
    MMA16816(ACC[B0 + 0], AL, Q0.x, Q0.y); \
    MMA16816(ACC[B0 + 1], AL, Q1.x, Q1.y); \
    MMA16816(ACC[B0 + 2], AL, Q2.x, Q2.y); \
    MMA16816(ACC[B0 + 3], AL, Q3.x, Q3.y); \
} while (0)

// ---------------- weight prep: fp32 -> bf16 hi/lo fragment-packed -----------
__global__ __launch_bounds__(256) void prep_weights(
    const float* __restrict__ Ws, const float* __restrict__ Wa,
    const float* __restrict__ Wc)
{
    int i = blockIdx.x * 256 + threadIdx.x;     // 0..65535 (one uint each)
    int stage = (i >= 16384) ? 1 : 0;
    int rem = stage ? (i - 16384) : i;
    int j    = rem & 3;
    int lane = (rem >> 2) & 31;
    int kt   = (rem >> 7) & 7;
    int nb   = rem >> 10;
    int gid = lane >> 2, tig = lane & 3;
    int n = nb * 8 + gid;
    int k = kt * 16 + ((j & 1) ? 8 : 0) + 2 * tig;
    float w0, w1;
    if (!stage)        { w0 = Ws[n * 128 + k];            w1 = Ws[n * 128 + k + 1]; }
    else if (n < 128)  { w0 = Wa[n * 128 + k];            w1 = Wa[n * 128 + k + 1]; }
    else if (n < 256)  { w0 = Wc[(n - 128) * 256 + k];    w1 = Wc[(n - 128) * 256 + k + 1]; }
    else               { w0 = Wc[(n - 256) * 256 + 128 + k];
                         w1 = Wc[(n - 256) * 256 + 128 + k + 1]; }
    unsigned hi, lo;
    split2(w0, w1, hi, lo);
    unsigned* dst = stage ? (unsigned*)g_WtP : (unsigned*)g_WsP;
    dst[((nb * 8 + kt) * 32 + lane) * 4 + j] = (j < 2) ? hi : lo;
}

// ---------------- K1: proj = X*Ws^T + bs  (persistent, smem weights) --------
#define K1_SMEM (16 * 8 * 32 * 16 + 512)     // 64KB frags + bias
__global__ __launch_bounds__(256) void proj_mma(
    const float* __restrict__ X, const float* __restrict__ bs)
{
    extern __shared__ char smem[];
    uint4* sW = (uint4*)smem;                          // [16*8*32]
    float* smbs = (float*)(smem + 16 * 8 * 32 * 16);   // [128]
    const int tid = threadIdx.x;
    for (int i = tid; i < 16 * 8 * 32; i += 256) sW[i] = g_WsP[i];
    if (tid < 128) smbs[tid] = bs[tid];
    __syncthreads();

    const int wid = tid >> 5, lane = tid & 31;
    const int gid = lane >> 2, tig = lane & 3;
    const int gstride = gridDim.x * 8;

    for (int g = blockIdx.x * 8 + wid; g < NGROUPS; g += gstride) {
        const size_t r0 = (size_t)g * 16 + gid;
        const size_t r1 = r0 + 8;
        const float* x0p = X + r0 * 128;
        const float* x1p = X + r1 * 128;

        float acc[16][4];
        #pragma unroll
        for (int b = 0; b < 16; b++)
            acc[b][0] = acc[b][1] = acc[b][2] = acc[b][3] = 0.f;

        #pragma unroll
        for (int kt = 0; kt < 8; kt++) {
            const int k0 = kt * 16;
            float2 xa = *(const float2*)(x0p + k0 + 2 * tig);
            float2 xb = *(const float2*)(x1p + k0 + 2 * tig);
            float2 xc = *(const float2*)(x0p + k0 + 8 + 2 * tig);
            float2 xd = *(const float2*)(x1p + k0 + 8 + 2 * tig);
            unsigned ah[4], al[4];
            split2(xa.x, xa.y, ah[0], al[0]);
            split2(xb.x, xb.y, ah[1], al[1]);
            split2(xc.x, xc.y, ah[2], al[2]);
            split2(xd.x, xd.y, ah[3], al[3]);
            #pragma unroll
            for (int bg = 0; bg < 4; bg++) {
                const int b0 = bg * 4;
                uint4 q0 = sW[((b0 + 0) * 8 + kt) * 32 + lane];
                uint4 q1 = sW[((b0 + 1) * 8 + kt) * 32 + lane];
                uint4 q2 = sW[((b0 + 2) * 8 + kt) * 32 + lane];
                uint4 q3 = sW[((b0 + 3) * 8 + kt) * 32 + lane];
                MMA_GROUP4(acc, b0, ah, al, q0, q1, q2, q3);
            }
        }

        #pragma unroll
        for (int b = 0; b < 16; b++) {
            const int c0 = 8 * b + 2 * tig;
            float b0v = smbs[c0], b1v = smbs[c0 + 1];
            *(float2*)(g_proj + r0 * 128 + c0) = make_float2(acc[b][0] + b0v, acc[b][1] + b1v);
            *(float2*)(g_proj + r1 * 128 + c0) = make_float2(acc[b][2] + b0v, acc[b][3] + b1v);
        }
    }
}

// ---------------- K2: Y = proj*[Wa;Wc1;Wc2]^T -> {u_t, X1b, X2} -------------
#define K2_SMEM (48 * 8 * 32 * 16 + 1536)    // 192KB frags + ba/va/bc
__global__ __launch_bounds__(256) void attn_mma(
    const float* __restrict__ ba, const float* __restrict__ va,
    const float* __restrict__ bc)
{
    extern __shared__ char smem[];
    uint4* sW = (uint4*)smem;                          // [48*8*32]
    float* smba = (float*)(smem + 48 * 8 * 32 * 16);
    float* smva = smba + 128;
    float* smbc = smva + 128;
    const int tid = threadIdx.x;
    for (int i = tid; i < 48 * 8 * 32; i += 256) sW[i] = g_WtP[i];
    if (tid < 128) {
        smba[tid] = ba[tid];
        smva[tid] = va[tid];
        smbc[tid] = bc[tid];
    }
    __syncthreads();

    const int wid = tid >> 5, lane = tid & 31;
    const int gid = lane >> 2, tig = lane & 3;
    const int gstride = gridDim.x * 8;

    for (int g = blockIdx.x * 8 + wid; g < NGROUPS; g += gstride) {
        const size_t r0 = (size_t)g * 16 + gid;
        const size_t r1 = r0 + 8;
        const float* p0 = g_proj + r0 * 128;
        const float* p1 = g_proj + r1 * 128;

        // A fragments for all 8 k-tiles (proj rows, bf16 hi/lo split)
        unsigned aph[8][4], apl[8][4];
        #pragma unroll
        for (int kt = 0; kt < 8; kt++) {
            const int k0 = kt * 16;
            float2 xa = *(const float2*)(p0 + k0 + 2 * tig);
            float2 xb = *(const float2*)(p1 + k0 + 2 * tig);
            float2 xc = *(const float2*)(p0 + k0 + 8 + 2 * tig);
            float2 xd = *(const float2*)(p1 + k0 + 8 + 2 * tig);
            split2(xa.x, xa.y, aph[kt][0], apl[kt][0]);
            split2(xb.x, xb.y, aph[kt][1], apl[kt][1]);
            split2(xc.x, xc.y, aph[kt][2], apl[kt][2]);
            split2(xd.x, xd.y, aph[kt][3], apl[kt][3]);
        }

        float ut0 = 0.f, ut1 = 0.f;
        #pragma unroll
        for (int chunk = 0; chunk < 6; chunk++) {
            float d[8][4];
            #pragma unroll
            for (int b = 0; b < 8; b++)
                d[b][0] = d[b][1] = d[b][2] = d[b][3] = 0.f;
            #pragma unroll
            for (int kt = 0; kt < 8; kt++) {
                #pragma unroll
                for (int bg = 0; bg < 2; bg++) {
                    const int b0 = bg * 4;
                    const int nbb = chunk * 8 + b0;
                    uint4 q0 = sW[((nbb + 0) * 8 + kt) * 32 + lane];
                    uint4 q1 = sW[((nbb + 1) * 8 + kt) * 32 + lane];
                    uint4 q2 = sW[((nbb + 2) * 8 + kt) * 32 + lane];
                    uint4 q3 = sW[((nbb + 3) * 8 + kt) * 32 + lane];
                    unsigned* ah = aph[kt];
                    unsigned* al = apl[kt];
                    MMA_GROUP4(d, b0, ah, al, q0, q1, q2, q3);
                }
            }
            if (chunk < 2) {
                // Wa part: u_t += va .* tanh(. + ba)
                #pragma unroll
                for (int b = 0; b < 8; b++) {
                    const int c0 = chunk * 64 + 8 * b + 2 * tig;
                    float ba0 = smba[c0], ba1 = smba[c0 + 1];
                    float va0 = smva[c0], va1 = smva[c0 + 1];
                    ut0 += va0 * tanhf(d[b][0] + ba0) + va1 * tanhf(d[b][1] + ba1);
                    ut1 += va0 * tanhf(d[b][2] + ba0) + va1 * tanhf(d[b][3] + ba1);
                }
            } else if (chunk < 4) {
                #pragma unroll
                for (int b = 0; b < 8; b++) {
                    const int c0 = (chunk - 2) * 64 + 8 * b + 2 * tig;
                    float bc0 = smbc[c0], bc1 = smbc[c0 + 1];
                    *(float2*)(g_X1b + r0 * 128 + c0) = make_float2(d[b][0] + bc0, d[b][1] + bc1);
                    *(float2*)(g_X1b + r1 * 128 + c0) = make_float2(d[b][2] + bc0, d[b][3] + bc1);
                }
            } else {
                #pragma unroll
                for (int b = 0; b < 8; b++) {
                    const int c0 = (chunk - 4) * 64 + 8 * b + 2 * tig;
                    *(float2*)(g_X2 + r0 * 128 + c0) = make_float2(d[b][0], d[b][1]);
                    *(float2*)(g_X2 + r1 * 128 + c0) = make_float2(d[b][2], d[b][3]);
                }
            }
        }
        // reduce u_t over the 4 lanes of each row group (tig axis)
        ut0 += __shfl_xor_sync(0xffffffffu, ut0, 1);
        ut0 += __shfl_xor_sync(0xffffffffu, ut0, 2);
        ut1 += __shfl_xor_sync(0xffffffffu, ut1, 1);
        ut1 += __shfl_xor_sync(0xffffffffu, ut1, 2);
        if (tig == 0) { g_ut[r0] = ut0; g_ut[r1] = ut1; }
    }
}

// ---------------- softmax over N=2048 per batch -----------------------------
__global__ __launch_bounds__(256) void softmax_rows(int which)
{
    const float* u = (which == 0) ? g_ut : g_ut2;
    float* p       = (which == 0) ? g_at : g_prob;
    const int b = blockIdx.x;
    const float* ub = u + (size_t)b * NN;
    float* pb = p + (size_t)b * NN;
    const int tid = threadIdx.x;
    __shared__ float sm[256];

    float mx = -1e30f;
    for (int i = tid; i < NN; i += 256) mx = fmaxf(mx, ub[i]);
    sm[tid] = mx; __syncthreads();
    for (int s = 128; s > 0; s >>= 1) {
        if (tid < s) sm[tid] = fmaxf(sm[tid], sm[tid + s]);
        __syncthreads();
    }
    mx = sm[0]; __syncthreads();

    float sum = 0.f;
    for (int i = tid; i < NN; i += 256) {
        float e = __expf(ub[i] - mx);
        pb[i] = e;
        sum += e;
    }
    sm[tid] = sum; __syncthreads();
    for (int s = 128; s > 0; s >>= 1) {
        if (tid < s) sm[tid] += sm[tid + s];
        __syncthreads();
    }
    float inv = 1.f / sm[0];
    for (int i = tid; i < NN; i += 256) pb[i] *= inv;
}

// ---------------- u_t_2 = vc . tanh(X1b + a_t * X2) -------------------------
__global__ __launch_bounds__(256) void compute_ut2(const float* __restrict__ vc)
{
    const int row = blockIdx.x * 8 + (threadIdx.x >> 5);
    const int lane = threadIdx.x & 31;
    const float a = g_at[row];
    float4 v1 = ((const float4*)(g_X1b + (size_t)row * 128))[lane];
    float4 v2 = ((const float4*)(g_X2 + (size_t)row * 128))[lane];
    float4 vv = ((const float4*)vc)[lane];
    float s = vv.x * tanhf(v1.x + a * v2.x)
            + vv.y * tanhf(v1.y + a * v2.y)
            + vv.z * tanhf(v1.z + a * v2.z)
            + vv.w * tanhf(v1.w + a * v2.w);
    #pragma unroll
    for (int off = 16; off > 0; off >>= 1)
        s += __shfl_xor_sync(0xffffffffu, s, off);
    if (lane == 0) g_ut2[row] = s;
}

// ---------------- h_i = sum_n prob * proj ----------------------------------
__global__ __launch_bounds__(256) void reduce_hi()
{
    const int b = blockIdx.x;
    const int e = threadIdx.x & 127;
    const int half = threadIdx.x >> 7;
    float s = 0.f;
    const float* pb = g_prob + (size_t)b * NN;
    const float* prb = g_proj + (size_t)b * NN * 128;
    for (int n = half; n < NN; n += 2)
        s = fmaf(pb[n], prb[(size_t)n * 128 + e], s);
    __shared__ float sm[256];
    sm[threadIdx.x] = s; __syncthreads();
    if (half == 0) g_hi[b * 128 + e] = sm[e] + sm[128 + e];
}

// ---------------- final MLP: v = W2 . relu(W1 h + b1) + b2 ------------------
__global__ __launch_bounds__(128) void final_mlp(
    const float* __restrict__ W1, const float* __restrict__ b1,
    const float* __restrict__ W2, const float* __restrict__ b2,
    float* __restrict__ out)
{
    const int b = blockIdx.x;
    const int e = threadIdx.x;
    __shared__ float h[128];
    __shared__ float sm[128];
    h[e] = g_hi[b * 128 + e];
    __syncthreads();
    float s = b1[e];
    #pragma unroll 8
    for (int k = 0; k < 128; k++) s = fmaf(W1[e * 128 + k], h[k], s);
    sm[e] = fmaxf(s, 0.f) * W2[e];
    __syncthreads();
    for (int st = 64; st > 0; st >>= 1) {
        if (e < st) sm[e] += sm[e + st];
        __syncthreads();
    }
    if (e == 0) out[b] = sm[0] + b2[0];
}

// ---------------- launch ----------------------------------------------------
// Canonical indices: 0 instance,1 W_s,2 b_s,3 W_a,4 b_a,5 v_a,6 W_c,7 b_c,
//                    8 v_c,9 W1,10 b1,11 W2,12 b2
extern "C" void kernel_launch(void* const* d_in, const int* in_sizes, int n_in,
                              void* d_out, int out_size)
{
    static const int sigA[13] = {33554432,16384,128,16384,128,128,32768,128,128,16384,128,128,1};
    static const int mapA[13] = {0,1,2,3,4,5,6,7,8,9,10,11,12};
    static const int sigB[13] = {16384,128,16384,32768,16384,128,1,128,128,128,33554432,128,128};
    static const int mapB[13] = {10,4,9,2,7,11,3,8,12,0,5,1,6};
    static const int sigC[13] = {128,1,128,128,128,33554432,128,128,16384,128,16384,32768,16384};
    static const int mapC[13] = {5,12,4,10,2,6,11,3,7,8,0,9,1};

    const int* map = mapA;
    bool okA = true, okB = true, okC = true;
    for (int i = 0; i < 13 && i < n_in; i++) {
        if (in_sizes[i] != sigA[i]) okA = false;
        if (in_sizes[i] != sigB[i]) okB = false;
        if (in_sizes[i] != sigC[i]) okC = false;
    }
    int fb_map[13];
    if (okA)      map = mapA;
    else if (okB) map = mapB;
    else if (okC) map = mapC;
    else {
        int next16 = 0, next128 = 0;
        static const int ord16[3]  = {1, 3, 9};
        static const int ord128[7] = {2, 4, 5, 7, 8, 10, 11};
        for (int i = 0; i < 13; i++) fb_map[i] = i;
        for (int p = 0; p < 13 && p < n_in; p++) {
            int s = in_sizes[p];
            if (s == 33554432)      fb_map[0] = p;
            else if (s == 32768)    fb_map[6] = p;
            else if (s == 1)        fb_map[12] = p;
            else if (s == 16384)  { if (next16 < 3)  fb_map[ord16[next16++]]  = p; }
            else if (s == 128)    { if (next128 < 7) fb_map[ord128[next128++]] = p; }
        }
        map = fb_map;
    }

    const float* X  = (const float*)d_in[map[0]];
    const float* Ws = (const float*)d_in[map[1]];
    const float* bs = (const float*)d_in[map[2]];
    const float* Wa = (const float*)d_in[map[3]];
    const float* ba = (const float*)d_in[map[4]];
    const float* va = (const float*)d_in[map[5]];
    const float* Wc = (const float*)d_in[map[6]];
    const float* bc = (const float*)d_in[map[7]];
    const float* vc = (const float*)d_in[map[8]];
    const float* W1 = (const float*)d_in[map[9]];
    const float* b1 = (const float*)d_in[map[10]];
    const float* W2 = (const float*)d_in[map[11]];
    const float* b2 = (const float*)d_in[map[12]];
    float* out = (float*)d_out;

    cudaFuncSetAttribute(proj_mma, cudaFuncAttributeMaxDynamicSharedMemorySize, K1_SMEM);
    cudaFuncSetAttribute(attn_mma, cudaFuncAttributeMaxDynamicSharedMemorySize, K2_SMEM);

    prep_weights<<<256, 256>>>(Ws, Wa, Wc);
    proj_mma<<<444, 256, K1_SMEM>>>(X, bs);
    attn_mma<<<148, 256, K2_SMEM>>>(ba, va, bc);
    softmax_rows<<<BB, 256>>>(0);
    compute_ut2<<<MT / 8, 256>>>(vc);
    softmax_rows<<<BB, 256>>>(1);
    reduce_hi<<<BB, 256>>>();
    final_mlp<<<BB, 128>>>(W1, b1, W2, b2, out);
}

// round 12
// speedup vs baseline: 2.3793x; 1.2243x over previous
#include <cuda_runtime.h>
#include <cuda_bf16.h>
#include <math.h>
#include <stdint.h>

// Problem constants
#define BB 128
#define NN 2048
#define EE 128
#define MT (BB * NN)   // 262144 total rows
#define NGROUPS (MT / 16)  // 16384 16-row groups

// ---------------- scratch (device globals; no allocation allowed) -----------
__device__ float g_proj[(size_t)MT * EE];   // [M,128]
__device__ float g_ut  [MT];
__device__ float g_at  [MT];
__device__ float g_ut2 [MT];
__device__ float g_prob[MT];
__device__ float g_hi  [BB * EE];

// Packed weight fragments (bf16 hi/lo, per-lane mma fragment order).
// Entry (nb*8+kt)*32+lane = {hi(k,k+1), hi(k+8,k+9), lo(k,k+1), lo(k+8,k+9)}
// with n = 8*nb+gid, k = 16*kt+2*tig.
__device__ uint4 g_WsP[16 * 8 * 32];        // Ws  [128 x 128]  -> 16 n-blocks
__device__ uint4 g_WtP[48 * 8 * 32];        // [Wa; Wc1; Wc2] [384 x 128] -> 48

__device__ __forceinline__ void split2(float x0, float x1,
                                       unsigned &hi, unsigned &lo) {
    __nv_bfloat16 h0 = __float2bfloat16_rn(x0);
    __nv_bfloat16 h1 = __float2bfloat16_rn(x1);
    float r0 = x0 - __bfloat162float(h0);
    float r1 = x1 - __bfloat162float(h1);
    __nv_bfloat162 hh; hh.x = h0; hh.y = h1;
    __nv_bfloat162 ll; ll.x = __float2bfloat16_rn(r0);
                       ll.y = __float2bfloat16_rn(r1);
    hi = *reinterpret_cast<unsigned*>(&hh);
    lo = *reinterpret_cast<unsigned*>(&ll);
}

#define MMA16816(d, a, b0_, b1_) \
  asm volatile("mma.sync.aligned.m16n8k16.row.col.f32.bf16.bf16.f32 " \
    "{%0,%1,%2,%3}, {%4,%5,%6,%7}, {%8,%9}, {%0,%1,%2,%3};" \
    : "+f"(d[0]), "+f"(d[1]), "+f"(d[2]), "+f"(d[3]) \
    : "r"(a[0]), "r"(a[1]), "r"(a[2]), "r"(a[3]), "r"(b0_), "r"(b1_))

// 12 MMAs over 4 independent accumulators (hi*Whi, hi*Wlo, lo*Whi),
// dependent distance 4 -> hides HMMA latency.
#define MMA_GROUP4(ACC, B0, AH, AL, Q0, Q1, Q2, Q3) do { \
    MMA16816(ACC[B0 + 0], AH, Q0.x, Q0.y); \
    MMA16816(ACC[B0 + 1], AH, Q1.x, Q1.y); \
    MMA16816(ACC[B0 + 2], AH, Q2.x, Q2.y); \
    MMA16816(ACC[B0 + 3], AH, Q3.x, Q3.y); \
    MMA16816(ACC[B0 + 0], AH, Q0.z, Q0.w); \
    MMA16816(ACC[B0 + 1], AH, Q1.z, Q1.w); \
    MMA16816(ACC[B0 + 2], AH, Q2.z, Q2.w); \
    MMA16816(ACC[B0 + 3], AH, Q3.z, Q3.w); \
    MMA16816(ACC[B0 + 0], AL, Q0.x, Q0.y); \
    MMA16816(ACC[B0 + 1], AL, Q1.x, Q1.y); \
    MMA16816(ACC[B0 + 2], AL, Q2.x, Q2.y); \
    MMA16816(ACC[B0 + 3], AL, Q3.x, Q3.y); \
} while (0)

// ---------------- weight prep: fp32 -> bf16 hi/lo fragment-packed -----------
__global__ __launch_bounds__(256) void prep_weights(
    const float* __restrict__ Ws, const float* __restrict__ Wa,
    const float* __restrict__ Wc)
{
    int i = blockIdx.x * 256 + threadIdx.x;     // 0..65535 (one uint each)
    int stage = (i >= 16384) ? 1 : 0;
    int rem = stage ? (i - 16384) : i;
    int j    = rem & 3;
    int lane = (rem >> 2) & 31;
    int kt   = (rem >> 7) & 7;
    int nb   = rem >> 10;
    int gid = lane >> 2, tig = lane & 3;
    int n = nb * 8 + gid;
    int k = kt * 16 + ((j & 1) ? 8 : 0) + 2 * tig;
    float w0, w1;
    if (!stage)        { w0 = Ws[n * 128 + k];            w1 = Ws[n * 128 + k + 1]; }
    else if (n < 128)  { w0 = Wa[n * 128 + k];            w1 = Wa[n * 128 + k + 1]; }
    else if (n < 256)  { w0 = Wc[(n - 128) * 256 + k];    w1 = Wc[(n - 128) * 256 + k + 1]; }
    else               { w0 = Wc[(n - 256) * 256 + 128 + k];
                         w1 = Wc[(n - 256) * 256 + 128 + k + 1]; }
    unsigned hi, lo;
    split2(w0, w1, hi, lo);
    unsigned* dst = stage ? (unsigned*)g_WtP : (unsigned*)g_WsP;
    dst[((nb * 8 + kt) * 32 + lane) * 4 + j] = (j < 2) ? hi : lo;
}

// ---------------- K1': proj = X*Ws^T + bs  AND  u_t  (persistent) -----------
// smem: Ws frags 64KB + Wa frags 64KB + bs/ba/va
#define K1_SMEM (2 * 16 * 8 * 32 * 16 + 1536)
__global__ __launch_bounds__(256) void proj_ut_mma(
    const float* __restrict__ X,  const float* __restrict__ bs,
    const float* __restrict__ ba, const float* __restrict__ va)
{
    extern __shared__ char smem[];
    uint4* sWs = (uint4*)smem;                              // [4096]
    uint4* sWa = (uint4*)(smem + 16 * 8 * 32 * 16);         // [4096]
    float* smbs = (float*)(smem + 2 * 16 * 8 * 32 * 16);
    float* smba = smbs + 128;
    float* smva = smba + 128;
    const int tid = threadIdx.x;
    for (int i = tid; i < 16 * 8 * 32; i += 256) {
        sWs[i] = g_WsP[i];
        sWa[i] = g_WtP[i];              // Wa = first 16 n-blocks of WtP
    }
    if (tid < 128) {
        smbs[tid] = bs[tid];
        smba[tid] = ba[tid];
        smva[tid] = va[tid];
    }
    __syncthreads();

    const int wid = tid >> 5, lane = tid & 31;
    const int gid = lane >> 2, tig = lane & 3;
    const int gstride = gridDim.x * 8;

    for (int g = blockIdx.x * 8 + wid; g < NGROUPS; g += gstride) {
        const size_t r0 = (size_t)g * 16 + gid;
        const size_t r1 = r0 + 8;
        const float* x0p = X + r0 * 128;
        const float* x1p = X + r1 * 128;

        // ---- stage A: proj ----
        float acc[16][4];
        #pragma unroll
        for (int b = 0; b < 16; b++)
            acc[b][0] = acc[b][1] = acc[b][2] = acc[b][3] = 0.f;

        #pragma unroll
        for (int kt = 0; kt < 8; kt++) {
            const int k0 = kt * 16;
            float2 xa = *(const float2*)(x0p + k0 + 2 * tig);
            float2 xb = *(const float2*)(x1p + k0 + 2 * tig);
            float2 xc = *(const float2*)(x0p + k0 + 8 + 2 * tig);
            float2 xd = *(const float2*)(x1p + k0 + 8 + 2 * tig);
            unsigned ah[4], al[4];
            split2(xa.x, xa.y, ah[0], al[0]);
            split2(xb.x, xb.y, ah[1], al[1]);
            split2(xc.x, xc.y, ah[2], al[2]);
            split2(xd.x, xd.y, ah[3], al[3]);
            #pragma unroll
            for (int bg = 0; bg < 4; bg++) {
                const int b0 = bg * 4;
                uint4 q0 = sWs[((b0 + 0) * 8 + kt) * 32 + lane];
                uint4 q1 = sWs[((b0 + 1) * 8 + kt) * 32 + lane];
                uint4 q2 = sWs[((b0 + 2) * 8 + kt) * 32 + lane];
                uint4 q3 = sWs[((b0 + 3) * 8 + kt) * 32 + lane];
                MMA_GROUP4(acc, b0, ah, al, q0, q1, q2, q3);
            }
        }

        // bias + store proj + build A'-frags (proj in bf16 hi/lo)
        unsigned aph[8][4], apl[8][4];
        #pragma unroll
        for (int b = 0; b < 16; b++) {
            const int c0 = 8 * b + 2 * tig;
            float b0v = smbs[c0], b1v = smbs[c0 + 1];
            acc[b][0] += b0v; acc[b][1] += b1v;
            acc[b][2] += b0v; acc[b][3] += b1v;
            *(float2*)(g_proj + r0 * 128 + c0) = make_float2(acc[b][0], acc[b][1]);
            *(float2*)(g_proj + r1 * 128 + c0) = make_float2(acc[b][2], acc[b][3]);
        }
        // D-frag -> A-frag identity: D cols of n-block pair (2kt, 2kt+1)
        // supply A' k-tile kt fragments.
        #pragma unroll
        for (int kt = 0; kt < 8; kt++) {
            split2(acc[2*kt  ][0], acc[2*kt  ][1], aph[kt][0], apl[kt][0]);
            split2(acc[2*kt  ][2], acc[2*kt  ][3], aph[kt][1], apl[kt][1]);
            split2(acc[2*kt+1][0], acc[2*kt+1][1], aph[kt][2], apl[kt][2]);
            split2(acc[2*kt+1][2], acc[2*kt+1][3], aph[kt][3], apl[kt][3]);
        }

        // ---- stage B: u_t = sum va.tanh(proj*Wa^T + ba) ----
        float ut0 = 0.f, ut1 = 0.f;
        #pragma unroll
        for (int chunk = 0; chunk < 2; chunk++) {
            float d[8][4];
            #pragma unroll
            for (int b = 0; b < 8; b++)
                d[b][0] = d[b][1] = d[b][2] = d[b][3] = 0.f;
            #pragma unroll
            for (int kt = 0; kt < 8; kt++) {
                #pragma unroll
                for (int bg = 0; bg < 2; bg++) {
                    const int b0 = bg * 4;
                    const int nbb = chunk * 8 + b0;
                    uint4 q0 = sWa[((nbb + 0) * 8 + kt) * 32 + lane];
                    uint4 q1 = sWa[((nbb + 1) * 8 + kt) * 32 + lane];
                    uint4 q2 = sWa[((nbb + 2) * 8 + kt) * 32 + lane];
                    uint4 q3 = sWa[((nbb + 3) * 8 + kt) * 32 + lane];
                    unsigned* ah = aph[kt];
                    unsigned* al = apl[kt];
                    MMA_GROUP4(d, b0, ah, al, q0, q1, q2, q3);
                }
            }
            #pragma unroll
            for (int b = 0; b < 8; b++) {
                const int c0 = chunk * 64 + 8 * b + 2 * tig;
                float ba0 = smba[c0], ba1 = smba[c0 + 1];
                float va0 = smva[c0], va1 = smva[c0 + 1];
                ut0 += va0 * tanhf(d[b][0] + ba0) + va1 * tanhf(d[b][1] + ba1);
                ut1 += va0 * tanhf(d[b][2] + ba0) + va1 * tanhf(d[b][3] + ba1);
            }
        }
        ut0 += __shfl_xor_sync(0xffffffffu, ut0, 1);
        ut0 += __shfl_xor_sync(0xffffffffu, ut0, 2);
        ut1 += __shfl_xor_sync(0xffffffffu, ut1, 1);
        ut1 += __shfl_xor_sync(0xffffffffu, ut1, 2);
        if (tig == 0) { g_ut[r0] = ut0; g_ut[r1] = ut1; }
    }
}

// ---------------- K3': ut2 = vc.tanh(Wc1*proj + bc + at*(Wc2*proj)) ---------
// X1b/X2 never touch DRAM: both halves computed in registers per chunk pair.
#define K3_SMEM (2 * 16 * 8 * 32 * 16 + 1024)
__global__ __launch_bounds__(256) void attn2_mma(
    const float* __restrict__ bc, const float* __restrict__ vc)
{
    extern __shared__ char smem[];
    uint4* sW1 = (uint4*)smem;                              // Wc1 frags
    uint4* sW2 = (uint4*)(smem + 16 * 8 * 32 * 16);         // Wc2 frags
    float* smbc = (float*)(smem + 2 * 16 * 8 * 32 * 16);
    float* smvc = smbc + 128;
    const int tid = threadIdx.x;
    for (int i = tid; i < 16 * 8 * 32; i += 256) {
        sW1[i] = g_WtP[16 * 8 * 32 + i];     // n-blocks 16..31
        sW2[i] = g_WtP[32 * 8 * 32 + i];     // n-blocks 32..47
    }
    if (tid < 128) {
        smbc[tid] = bc[tid];
        smvc[tid] = vc[tid];
    }
    __syncthreads();

    const int wid = tid >> 5, lane = tid & 31;
    const int gid = lane >> 2, tig = lane & 3;
    const int gstride = gridDim.x * 8;

    for (int g = blockIdx.x * 8 + wid; g < NGROUPS; g += gstride) {
        const size_t r0 = (size_t)g * 16 + gid;
        const size_t r1 = r0 + 8;
        const float* p0 = g_proj + r0 * 128;
        const float* p1 = g_proj + r1 * 128;
        const float a0 = g_at[r0];
        const float a1 = g_at[r1];

        unsigned aph[8][4], apl[8][4];
        #pragma unroll
        for (int kt = 0; kt < 8; kt++) {
            const int k0 = kt * 16;
            float2 xa = *(const float2*)(p0 + k0 + 2 * tig);
            float2 xb = *(const float2*)(p1 + k0 + 2 * tig);
            float2 xc = *(const float2*)(p0 + k0 + 8 + 2 * tig);
            float2 xd = *(const float2*)(p1 + k0 + 8 + 2 * tig);
            split2(xa.x, xa.y, aph[kt][0], apl[kt][0]);
            split2(xb.x, xb.y, aph[kt][1], apl[kt][1]);
            split2(xc.x, xc.y, aph[kt][2], apl[kt][2]);
            split2(xd.x, xd.y, aph[kt][3], apl[kt][3]);
        }

        float ut0 = 0.f, ut1 = 0.f;
        #pragma unroll
        for (int half = 0; half < 2; half++) {
            float d1[8][4], d2[8][4];
            #pragma unroll
            for (int b = 0; b < 8; b++) {
                d1[b][0] = d1[b][1] = d1[b][2] = d1[b][3] = 0.f;
                d2[b][0] = d2[b][1] = d2[b][2] = d2[b][3] = 0.f;
            }
            #pragma unroll
            for (int kt = 0; kt < 8; kt++) {
                unsigned* ah = aph[kt];
                unsigned* al = apl[kt];
                #pragma unroll
                for (int bg = 0; bg < 2; bg++) {
                    const int b0 = bg * 4;
                    const int nbb = half * 8 + b0;
                    uint4 q0 = sW1[((nbb + 0) * 8 + kt) * 32 + lane];
                    uint4 q1 = sW1[((nbb + 1) * 8 + kt) * 32 + lane];
                    uint4 q2 = sW1[((nbb + 2) * 8 + kt) * 32 + lane];
                    uint4 q3 = sW1[((nbb + 3) * 8 + kt) * 32 + lane];
                    MMA_GROUP4(d1, b0, ah, al, q0, q1, q2, q3);
                    uint4 p0q = sW2[((nbb + 0) * 8 + kt) * 32 + lane];
                    uint4 p1q = sW2[((nbb + 1) * 8 + kt) * 32 + lane];
                    uint4 p2q = sW2[((nbb + 2) * 8 + kt) * 32 + lane];
                    uint4 p3q = sW2[((nbb + 3) * 8 + kt) * 32 + lane];
                    MMA_GROUP4(d2, b0, ah, al, p0q, p1q, p2q, p3q);
                }
            }
            #pragma unroll
            for (int b = 0; b < 8; b++) {
                const int c0 = half * 64 + 8 * b + 2 * tig;
                float bc0 = smbc[c0], bc1 = smbc[c0 + 1];
                float vc0 = smvc[c0], vc1 = smvc[c0 + 1];
                ut0 += vc0 * tanhf(d1[b][0] + bc0 + a0 * d2[b][0])
                     + vc1 * tanhf(d1[b][1] + bc1 + a0 * d2[b][1]);
                ut1 += vc0 * tanhf(d1[b][2] + bc0 + a1 * d2[b][2])
                     + vc1 * tanhf(d1[b][3] + bc1 + a1 * d2[b][3]);
            }
        }
        ut0 += __shfl_xor_sync(0xffffffffu, ut0, 1);
        ut0 += __shfl_xor_sync(0xffffffffu, ut0, 2);
        ut1 += __shfl_xor_sync(0xffffffffu, ut1, 1);
        ut1 += __shfl_xor_sync(0xffffffffu, ut1, 2);
        if (tig == 0) { g_ut2[r0] = ut0; g_ut2[r1] = ut1; }
    }
}

// ---------------- softmax over N=2048 per batch -----------------------------
__global__ __launch_bounds__(256) void softmax_rows(int which)
{
    const float* u = (which == 0) ? g_ut : g_ut2;
    float* p       = (which == 0) ? g_at : g_prob;
    const int b = blockIdx.x;
    const float* ub = u + (size_t)b * NN;
    float* pb = p + (size_t)b * NN;
    const int tid = threadIdx.x;
    __shared__ float sm[256];

    float mx = -1e30f;
    for (int i = tid; i < NN; i += 256) mx = fmaxf(mx, ub[i]);
    sm[tid] = mx; __syncthreads();
    for (int s = 128; s > 0; s >>= 1) {
        if (tid < s) sm[tid] = fmaxf(sm[tid], sm[tid + s]);
        __syncthreads();
    }
    mx = sm[0]; __syncthreads();

    float sum = 0.f;
    for (int i = tid; i < NN; i += 256) {
        float e = __expf(ub[i] - mx);
        pb[i] = e;
        sum += e;
    }
    sm[tid] = sum; __syncthreads();
    for (int s = 128; s > 0; s >>= 1) {
        if (tid < s) sm[tid] += sm[tid + s];
        __syncthreads();
    }
    float inv = 1.f / sm[0];
    for (int i = tid; i < NN; i += 256) pb[i] *= inv;
}

// ---------------- h_i = sum_n prob * proj ----------------------------------
__global__ __launch_bounds__(256) void reduce_hi()
{
    const int b = blockIdx.x;
    const int e = threadIdx.x & 127;
    const int half = threadIdx.x >> 7;
    float s = 0.f;
    const float* pb = g_prob + (size_t)b * NN;
    const float* prb = g_proj + (size_t)b * NN * 128;
    for (int n = half; n < NN; n += 2)
        s = fmaf(pb[n], prb[(size_t)n * 128 + e], s);
    __shared__ float sm[256];
    sm[threadIdx.x] = s; __syncthreads();
    if (half == 0) g_hi[b * 128 + e] = sm[e] + sm[128 + e];
}

// ---------------- final MLP: v = W2 . relu(W1 h + b1) + b2 ------------------
__global__ __launch_bounds__(128) void final_mlp(
    const float* __restrict__ W1, const float* __restrict__ b1,
    const float* __restrict__ W2, const float* __restrict__ b2,
    float* __restrict__ out)
{
    const int b = blockIdx.x;
    const int e = threadIdx.x;
    __shared__ float h[128];
    __shared__ float sm[128];
    h[e] = g_hi[b * 128 + e];
    __syncthreads();
    float s = b1[e];
    #pragma unroll 8
    for (int k = 0; k < 128; k++) s = fmaf(W1[e * 128 + k], h[k], s);
    sm[e] = fmaxf(s, 0.f) * W2[e];
    __syncthreads();
    for (int st = 64; st > 0; st >>= 1) {
        if (e < st) sm[e] += sm[e + st];
        __syncthreads();
    }
    if (e == 0) out[b] = sm[0] + b2[0];
}

// ---------------- launch ----------------------------------------------------
// Canonical indices: 0 instance,1 W_s,2 b_s,3 W_a,4 b_a,5 v_a,6 W_c,7 b_c,
//                    8 v_c,9 W1,10 b1,11 W2,12 b2
extern "C" void kernel_launch(void* const* d_in, const int* in_sizes, int n_in,
                              void* d_out, int out_size)
{
    static const int sigA[13] = {33554432,16384,128,16384,128,128,32768,128,128,16384,128,128,1};
    static const int mapA[13] = {0,1,2,3,4,5,6,7,8,9,10,11,12};
    static const int sigB[13] = {16384,128,16384,32768,16384,128,1,128,128,128,33554432,128,128};
    static const int mapB[13] = {10,4,9,2,7,11,3,8,12,0,5,1,6};
    static const int sigC[13] = {128,1,128,128,128,33554432,128,128,16384,128,16384,32768,16384};
    static const int mapC[13] = {5,12,4,10,2,6,11,3,7,8,0,9,1};

    const int* map = mapA;
    bool okA = true, okB = true, okC = true;
    for (int i = 0; i < 13 && i < n_in; i++) {
        if (in_sizes[i] != sigA[i]) okA = false;
        if (in_sizes[i] != sigB[i]) okB = false;
        if (in_sizes[i] != sigC[i]) okC = false;
    }
    int fb_map[13];
    if (okA)      map = mapA;
    else if (okB) map = mapB;
    else if (okC) map = mapC;
    else {
        int next16 = 0, next128 = 0;
        static const int ord16[3]  = {1, 3, 9};
        static const int ord128[7] = {2, 4, 5, 7, 8, 10, 11};
        for (int i = 0; i < 13; i++) fb_map[i] = i;
        for (int p = 0; p < 13 && p < n_in; p++) {
            int s = in_sizes[p];
            if (s == 33554432)      fb_map[0] = p;
            else if (s == 32768)    fb_map[6] = p;
            else if (s == 1)        fb_map[12] = p;
            else if (s == 16384)  { if (next16 < 3)  fb_map[ord16[next16++]]  = p; }
            else if (s == 128)    { if (next128 < 7) fb_map[ord128[next128++]] = p; }
        }
        map = fb_map;
    }

    const float* X  = (const float*)d_in[map[0]];
    const float* Ws = (const float*)d_in[map[1]];
    const float* bs = (const float*)d_in[map[2]];
    const float* Wa = (const float*)d_in[map[3]];
    const float* ba = (const float*)d_in[map[4]];
    const float* va = (const float*)d_in[map[5]];
    const float* Wc = (const float*)d_in[map[6]];
    const float* bc = (const float*)d_in[map[7]];
    const float* vc = (const float*)d_in[map[8]];
    const float* W1 = (const float*)d_in[map[9]];
    const float* b1 = (const float*)d_in[map[10]];
    const float* W2 = (const float*)d_in[map[11]];
    const float* b2 = (const float*)d_in[map[12]];
    float* out = (float*)d_out;

    cudaFuncSetAttribute(proj_ut_mma, cudaFuncAttributeMaxDynamicSharedMemorySize, K1_SMEM);
    cudaFuncSetAttribute(attn2_mma,  cudaFuncAttributeMaxDynamicSharedMemorySize, K3_SMEM);

    prep_weights<<<256, 256>>>(Ws, Wa, Wc);
    proj_ut_mma<<<148, 256, K1_SMEM>>>(X, bs, ba, va);
    softmax_rows<<<BB, 256>>>(0);
    attn2_mma<<<148, 256, K3_SMEM>>>(bc, vc);
    softmax_rows<<<BB, 256>>>(1);
    reduce_hi<<<BB, 256>>>();
    final_mlp<<<BB, 128>>>(W1, b1, W2, b2, out);
}

// round 13
// speedup vs baseline: 2.4545x; 1.0316x over previous
#include <cuda_runtime.h>
#include <cuda_bf16.h>
#include <math.h>
#include <stdint.h>

// Problem constants
#define BB 128
#define NN 2048
#define EE 128
#define MT (BB * NN)   // 262144 total rows
#define NGROUPS (MT / 16)  // 16384 16-row groups

// ---------------- scratch (device globals; no allocation allowed) -----------
__device__ float g_proj[(size_t)MT * EE];   // [M,128]
__device__ float g_ut  [MT];
__device__ float g_at  [MT];
__device__ float g_ut2 [MT];
__device__ float g_prob[MT];
__device__ float g_hi  [BB * EE];

// Packed weight fragments (bf16 hi/lo, per-lane mma fragment order).
// Entry (nb*8+kt)*32+lane = {hi(k,k+1), hi(k+8,k+9), lo(k,k+1), lo(k+8,k+9)}
// with n = 8*nb+gid, k = 16*kt+2*tig.
__device__ uint4 g_WsP[16 * 8 * 32];        // Ws  [128 x 128]  -> 16 n-blocks
__device__ uint4 g_WtP[48 * 8 * 32];        // [Wa; Wc1; Wc2] [384 x 128] -> 48

__device__ __forceinline__ void split2(float x0, float x1,
                                       unsigned &hi, unsigned &lo) {
    __nv_bfloat16 h0 = __float2bfloat16_rn(x0);
    __nv_bfloat16 h1 = __float2bfloat16_rn(x1);
    float r0 = x0 - __bfloat162float(h0);
    float r1 = x1 - __bfloat162float(h1);
    __nv_bfloat162 hh; hh.x = h0; hh.y = h1;
    __nv_bfloat162 ll; ll.x = __float2bfloat16_rn(r0);
                       ll.y = __float2bfloat16_rn(r1);
    hi = *reinterpret_cast<unsigned*>(&hh);
    lo = *reinterpret_cast<unsigned*>(&ll);
}

#define MMA16816(d, a, b0_, b1_) \
  asm volatile("mma.sync.aligned.m16n8k16.row.col.f32.bf16.bf16.f32 " \
    "{%0,%1,%2,%3}, {%4,%5,%6,%7}, {%8,%9}, {%0,%1,%2,%3};" \
    : "+f"(d[0]), "+f"(d[1]), "+f"(d[2]), "+f"(d[3]) \
    : "r"(a[0]), "r"(a[1]), "r"(a[2]), "r"(a[3]), "r"(b0_), "r"(b1_))

// 12 MMAs over 4 independent accumulators (hi*Whi, hi*Wlo, lo*Whi),
// dependent distance 4 -> hides HMMA latency.
#define MMA_GROUP4(ACC, B0, AH, AL, Q0, Q1, Q2, Q3) do { \
    MMA16816(ACC[B0 + 0], AH, Q0.x, Q0.y); \
    MMA16816(ACC[B0 + 1], AH, Q1.x, Q1.y); \
    MMA16816(ACC[B0 + 2], AH, Q2.x, Q2.y); \
    MMA16816(ACC[B0 + 3], AH, Q3.x, Q3.y); \
    MMA16816(ACC[B0 + 0], AH, Q0.z, Q0.w); \
    MMA16816(ACC[B0 + 1], AH, Q1.z, Q1.w); \
    MMA16816(ACC[B0 + 2], AH, Q2.z, Q2.w); \
    MMA16816(ACC[B0 + 3], AH, Q3.z, Q3.w); \
    MMA16816(ACC[B0 + 0], AL, Q0.x, Q0.y); \
    MMA16816(ACC[B0 + 1], AL, Q1.x, Q1.y); \
    MMA16816(ACC[B0 + 2], AL, Q2.x, Q2.y); \
    MMA16816(ACC[B0 + 3], AL, Q3.x, Q3.y); \
} while (0)

// ---------------- weight prep: fp32 -> bf16 hi/lo fragment-packed -----------
__global__ __launch_bounds__(256) void prep_weights(
    const float* __restrict__ Ws, const float* __restrict__ Wa,
    const float* __restrict__ Wc)
{
    int i = blockIdx.x * 256 + threadIdx.x;     // 0..65535 (one uint each)
    int stage = (i >= 16384) ? 1 : 0;
    int rem = stage ? (i - 16384) : i;
    int j    = rem & 3;
    int lane = (rem >> 2) & 31;
    int kt   = (rem >> 7) & 7;
    int nb   = rem >> 10;
    int gid = lane >> 2, tig = lane & 3;
    int n = nb * 8 + gid;
    int k = kt * 16 + ((j & 1) ? 8 : 0) + 2 * tig;
    float w0, w1;
    if (!stage)        { w0 = Ws[n * 128 + k];            w1 = Ws[n * 128 + k + 1]; }
    else if (n < 128)  { w0 = Wa[n * 128 + k];            w1 = Wa[n * 128 + k + 1]; }
    else if (n < 256)  { w0 = Wc[(n - 128) * 256 + k];    w1 = Wc[(n - 128) * 256 + k + 1]; }
    else               { w0 = Wc[(n - 256) * 256 + 128 + k];
                         w1 = Wc[(n - 256) * 256 + 128 + k + 1]; }
    unsigned hi, lo;
    split2(w0, w1, hi, lo);
    unsigned* dst = stage ? (unsigned*)g_WtP : (unsigned*)g_WsP;
    dst[((nb * 8 + kt) * 32 + lane) * 4 + j] = (j < 2) ? hi : lo;
}

// ---------------- K1': proj = X*Ws^T + bs  AND  u_t  (persistent) -----------
// smem: Ws frags 64KB + Wa frags 64KB + bs/ba/va. 384 threads for occupancy.
#define K1_SMEM (2 * 16 * 8 * 32 * 16 + 1536)
__global__ __launch_bounds__(384) void proj_ut_mma(
    const float* __restrict__ X,  const float* __restrict__ bs,
    const float* __restrict__ ba, const float* __restrict__ va)
{
    extern __shared__ char smem[];
    uint4* sWs = (uint4*)smem;                              // [4096]
    uint4* sWa = (uint4*)(smem + 16 * 8 * 32 * 16);         // [4096]
    float* smbs = (float*)(smem + 2 * 16 * 8 * 32 * 16);
    float* smba = smbs + 128;
    float* smva = smba + 128;
    const int tid = threadIdx.x;
    for (int i = tid; i < 16 * 8 * 32; i += 384) {
        sWs[i] = g_WsP[i];
        sWa[i] = g_WtP[i];              // Wa = first 16 n-blocks of WtP
    }
    if (tid < 128) {
        smbs[tid] = bs[tid];
        smba[tid] = ba[tid];
        smva[tid] = va[tid];
    }
    __syncthreads();

    const int wid = tid >> 5, lane = tid & 31;
    const int gid = lane >> 2, tig = lane & 3;
    const int gstride = gridDim.x * 12;

    for (int g = blockIdx.x * 12 + wid; g < NGROUPS; g += gstride) {
        const size_t r0 = (size_t)g * 16 + gid;
        const size_t r1 = r0 + 8;
        const float* x0p = X + r0 * 128;
        const float* x1p = X + r1 * 128;

        // ---- stage A: proj ----
        float acc[16][4];
        #pragma unroll
        for (int b = 0; b < 16; b++)
            acc[b][0] = acc[b][1] = acc[b][2] = acc[b][3] = 0.f;

        #pragma unroll
        for (int kt = 0; kt < 8; kt++) {
            const int k0 = kt * 16;
            float2 xa = *(const float2*)(x0p + k0 + 2 * tig);
            float2 xb = *(const float2*)(x1p + k0 + 2 * tig);
            float2 xc = *(const float2*)(x0p + k0 + 8 + 2 * tig);
            float2 xd = *(const float2*)(x1p + k0 + 8 + 2 * tig);
            unsigned ah[4], al[4];
            split2(xa.x, xa.y, ah[0], al[0]);
            split2(xb.x, xb.y, ah[1], al[1]);
            split2(xc.x, xc.y, ah[2], al[2]);
            split2(xd.x, xd.y, ah[3], al[3]);
            #pragma unroll
            for (int bg = 0; bg < 4; bg++) {
                const int b0 = bg * 4;
                uint4 q0 = sWs[((b0 + 0) * 8 + kt) * 32 + lane];
                uint4 q1 = sWs[((b0 + 1) * 8 + kt) * 32 + lane];
                uint4 q2 = sWs[((b0 + 2) * 8 + kt) * 32 + lane];
                uint4 q3 = sWs[((b0 + 3) * 8 + kt) * 32 + lane];
                MMA_GROUP4(acc, b0, ah, al, q0, q1, q2, q3);
            }
        }

        // bias + store proj
        #pragma unroll
        for (int b = 0; b < 16; b++) {
            const int c0 = 8 * b + 2 * tig;
            float b0v = smbs[c0], b1v = smbs[c0 + 1];
            acc[b][0] += b0v; acc[b][1] += b1v;
            acc[b][2] += b0v; acc[b][3] += b1v;
            *(float2*)(g_proj + r0 * 128 + c0) = make_float2(acc[b][0], acc[b][1]);
            *(float2*)(g_proj + r1 * 128 + c0) = make_float2(acc[b][2], acc[b][3]);
        }

        // ---- stage B: u_t = sum va.tanh(proj*Wa^T + ba) ----
        // A-frags re-split from acc per kt inside the chunk loop (keeps regs low).
        float ut0 = 0.f, ut1 = 0.f;
        #pragma unroll 1
        for (int chunk = 0; chunk < 2; chunk++) {
            float d[8][4];
            #pragma unroll
            for (int b = 0; b < 8; b++)
                d[b][0] = d[b][1] = d[b][2] = d[b][3] = 0.f;
            #pragma unroll
            for (int kt = 0; kt < 8; kt++) {
                unsigned ah[4], al[4];
                split2(acc[2*kt  ][0], acc[2*kt  ][1], ah[0], al[0]);
                split2(acc[2*kt  ][2], acc[2*kt  ][3], ah[1], al[1]);
                split2(acc[2*kt+1][0], acc[2*kt+1][1], ah[2], al[2]);
                split2(acc[2*kt+1][2], acc[2*kt+1][3], ah[3], al[3]);
                #pragma unroll
                for (int bg = 0; bg < 2; bg++) {
                    const int b0 = bg * 4;
                    const int nbb = chunk * 8 + b0;
                    uint4 q0 = sWa[((nbb + 0) * 8 + kt) * 32 + lane];
                    uint4 q1 = sWa[((nbb + 1) * 8 + kt) * 32 + lane];
                    uint4 q2 = sWa[((nbb + 2) * 8 + kt) * 32 + lane];
                    uint4 q3 = sWa[((nbb + 3) * 8 + kt) * 32 + lane];
                    MMA_GROUP4(d, b0, ah, al, q0, q1, q2, q3);
                }
            }
            #pragma unroll
            for (int b = 0; b < 8; b++) {
                const int c0 = chunk * 64 + 8 * b + 2 * tig;
                float ba0 = smba[c0], ba1 = smba[c0 + 1];
                float va0 = smva[c0], va1 = smva[c0 + 1];
                ut0 += va0 * tanhf(d[b][0] + ba0) + va1 * tanhf(d[b][1] + ba1);
                ut1 += va0 * tanhf(d[b][2] + ba0) + va1 * tanhf(d[b][3] + ba1);
            }
        }
        ut0 += __shfl_xor_sync(0xffffffffu, ut0, 1);
        ut0 += __shfl_xor_sync(0xffffffffu, ut0, 2);
        ut1 += __shfl_xor_sync(0xffffffffu, ut1, 1);
        ut1 += __shfl_xor_sync(0xffffffffu, ut1, 2);
        if (tig == 0) { g_ut[r0] = ut0; g_ut[r1] = ut1; }
    }
}

// ---------------- K3': ut2 = vc.tanh(Wc1*proj + bc + at*(Wc2*proj)) ---------
// X1b/X2 never touch DRAM. A-frags re-read from gmem per half (L2-hot),
// split per-kt transiently -> low registers, 384 threads.
#define K3_SMEM (2 * 16 * 8 * 32 * 16 + 1024)
__global__ __launch_bounds__(384) void attn2_mma(
    const float* __restrict__ bc, const float* __restrict__ vc)
{
    extern __shared__ char smem[];
    uint4* sW1 = (uint4*)smem;                              // Wc1 frags
    uint4* sW2 = (uint4*)(smem + 16 * 8 * 32 * 16);         // Wc2 frags
    float* smbc = (float*)(smem + 2 * 16 * 8 * 32 * 16);
    float* smvc = smbc + 128;
    const int tid = threadIdx.x;
    for (int i = tid; i < 16 * 8 * 32; i += 384) {
        sW1[i] = g_WtP[16 * 8 * 32 + i];     // n-blocks 16..31
        sW2[i] = g_WtP[32 * 8 * 32 + i];     // n-blocks 32..47
    }
    if (tid < 128) {
        smbc[tid] = bc[tid];
        smvc[tid] = vc[tid];
    }
    __syncthreads();

    const int wid = tid >> 5, lane = tid & 31;
    const int gid = lane >> 2, tig = lane & 3;
    const int gstride = gridDim.x * 12;

    for (int g = blockIdx.x * 12 + wid; g < NGROUPS; g += gstride) {
        const size_t r0 = (size_t)g * 16 + gid;
        const size_t r1 = r0 + 8;
        const float* p0 = g_proj + r0 * 128;
        const float* p1 = g_proj + r1 * 128;
        const float a0 = g_at[r0];
        const float a1 = g_at[r1];

        float ut0 = 0.f, ut1 = 0.f;
        #pragma unroll 1
        for (int half = 0; half < 2; half++) {
            float d1[8][4], d2[8][4];
            #pragma unroll
            for (int b = 0; b < 8; b++) {
                d1[b][0] = d1[b][1] = d1[b][2] = d1[b][3] = 0.f;
                d2[b][0] = d2[b][1] = d2[b][2] = d2[b][3] = 0.f;
            }
            #pragma unroll
            for (int kt = 0; kt < 8; kt++) {
                const int k0 = kt * 16;
                float2 xa = *(const float2*)(p0 + k0 + 2 * tig);
                float2 xb = *(const float2*)(p1 + k0 + 2 * tig);
                float2 xc = *(const float2*)(p0 + k0 + 8 + 2 * tig);
                float2 xd = *(const float2*)(p1 + k0 + 8 + 2 * tig);
                unsigned ah[4], al[4];
                split2(xa.x, xa.y, ah[0], al[0]);
                split2(xb.x, xb.y, ah[1], al[1]);
                split2(xc.x, xc.y, ah[2], al[2]);
                split2(xd.x, xd.y, ah[3], al[3]);
                #pragma unroll
                for (int bg = 0; bg < 2; bg++) {
                    const int b0 = bg * 4;
                    const int nbb = half * 8 + b0;
                    uint4 q0 = sW1[((nbb + 0) * 8 + kt) * 32 + lane];
                    uint4 q1 = sW1[((nbb + 1) * 8 + kt) * 32 + lane];
                    uint4 q2 = sW1[((nbb + 2) * 8 + kt) * 32 + lane];
                    uint4 q3 = sW1[((nbb + 3) * 8 + kt) * 32 + lane];
                    MMA_GROUP4(d1, b0, ah, al, q0, q1, q2, q3);
                    uint4 p0q = sW2[((nbb + 0) * 8 + kt) * 32 + lane];
                    uint4 p1q = sW2[((nbb + 1) * 8 + kt) * 32 + lane];
                    uint4 p2q = sW2[((nbb + 2) * 8 + kt) * 32 + lane];
                    uint4 p3q = sW2[((nbb + 3) * 8 + kt) * 32 + lane];
                    MMA_GROUP4(d2, b0, ah, al, p0q, p1q, p2q, p3q);
                }
            }
            #pragma unroll
            for (int b = 0; b < 8; b++) {
                const int c0 = half * 64 + 8 * b + 2 * tig;
                float bc0 = smbc[c0], bc1 = smbc[c0 + 1];
                float vc0 = smvc[c0], vc1 = smvc[c0 + 1];
                ut0 += vc0 * tanhf(d1[b][0] + bc0 + a0 * d2[b][0])
                     + vc1 * tanhf(d1[b][1] + bc1 + a0 * d2[b][1]);
                ut1 += vc0 * tanhf(d1[b][2] + bc0 + a1 * d2[b][2])
                     + vc1 * tanhf(d1[b][3] + bc1 + a1 * d2[b][3]);
            }
        }
        ut0 += __shfl_xor_sync(0xffffffffu, ut0, 1);
        ut0 += __shfl_xor_sync(0xffffffffu, ut0, 2);
        ut1 += __shfl_xor_sync(0xffffffffu, ut1, 1);
        ut1 += __shfl_xor_sync(0xffffffffu, ut1, 2);
        if (tig == 0) { g_ut2[r0] = ut0; g_ut2[r1] = ut1; }
    }
}

// ---------------- softmax over N=2048 per batch -----------------------------
__global__ __launch_bounds__(256) void softmax_rows(int which)
{
    const float* u = (which == 0) ? g_ut : g_ut2;
    float* p       = (which == 0) ? g_at : g_prob;
    const int b = blockIdx.x;
    const float* ub = u + (size_t)b * NN;
    float* pb = p + (size_t)b * NN;
    const int tid = threadIdx.x;
    __shared__ float sm[256];

    float mx = -1e30f;
    for (int i = tid; i < NN; i += 256) mx = fmaxf(mx, ub[i]);
    sm[tid] = mx; __syncthreads();
    for (int s = 128; s > 0; s >>= 1) {
        if (tid < s) sm[tid] = fmaxf(sm[tid], sm[tid + s]);
        __syncthreads();
    }
    mx = sm[0]; __syncthreads();

    float sum = 0.f;
    for (int i = tid; i < NN; i += 256) {
        float e = __expf(ub[i] - mx);
        pb[i] = e;
        sum += e;
    }
    sm[tid] = sum; __syncthreads();
    for (int s = 128; s > 0; s >>= 1) {
        if (tid < s) sm[tid] += sm[tid + s];
        __syncthreads();
    }
    float inv = 1.f / sm[0];
    for (int i = tid; i < NN; i += 256) pb[i] *= inv;
}

// ---------------- h_i = sum_n prob * proj ----------------------------------
__global__ __launch_bounds__(256) void reduce_hi()
{
    const int b = blockIdx.x;
    const int e = threadIdx.x & 127;
    const int half = threadIdx.x >> 7;
    float s = 0.f;
    const float* pb = g_prob + (size_t)b * NN;
    const float* prb = g_proj + (size_t)b * NN * 128;
    for (int n = half; n < NN; n += 2)
        s = fmaf(pb[n], prb[(size_t)n * 128 + e], s);
    __shared__ float sm[256];
    sm[threadIdx.x] = s; __syncthreads();
    if (half == 0) g_hi[b * 128 + e] = sm[e] + sm[128 + e];
}

// ---------------- final MLP: v = W2 . relu(W1 h + b1) + b2 ------------------
__global__ __launch_bounds__(128) void final_mlp(
    const float* __restrict__ W1, const float* __restrict__ b1,
    const float* __restrict__ W2, const float* __restrict__ b2,
    float* __restrict__ out)
{
    const int b = blockIdx.x;
    const int e = threadIdx.x;
    __shared__ float h[128];
    __shared__ float sm[128];
    h[e] = g_hi[b * 128 + e];
    __syncthreads();
    float s = b1[e];
    #pragma unroll 8
    for (int k = 0; k < 128; k++) s = fmaf(W1[e * 128 + k], h[k], s);
    sm[e] = fmaxf(s, 0.f) * W2[e];
    __syncthreads();
    for (int st = 64; st > 0; st >>= 1) {
        if (e < st) sm[e] += sm[e + st];
        __syncthreads();
    }
    if (e == 0) out[b] = sm[0] + b2[0];
}

// ---------------- launch ----------------------------------------------------
// Canonical indices: 0 instance,1 W_s,2 b_s,3 W_a,4 b_a,5 v_a,6 W_c,7 b_c,
//                    8 v_c,9 W1,10 b1,11 W2,12 b2
extern "C" void kernel_launch(void* const* d_in, const int* in_sizes, int n_in,
                              void* d_out, int out_size)
{
    static const int sigA[13] = {33554432,16384,128,16384,128,128,32768,128,128,16384,128,128,1};
    static const int mapA[13] = {0,1,2,3,4,5,6,7,8,9,10,11,12};
    static const int sigB[13] = {16384,128,16384,32768,16384,128,1,128,128,128,33554432,128,128};
    static const int mapB[13] = {10,4,9,2,7,11,3,8,12,0,5,1,6};
    static const int sigC[13] = {128,1,128,128,128,33554432,128,128,16384,128,16384,32768,16384};
    static const int mapC[13] = {5,12,4,10,2,6,11,3,7,8,0,9,1};

    const int* map = mapA;
    bool okA = true, okB = true, okC = true;
    for (int i = 0; i < 13 && i < n_in; i++) {
        if (in_sizes[i] != sigA[i]) okA = false;
        if (in_sizes[i] != sigB[i]) okB = false;
        if (in_sizes[i] != sigC[i]) okC = false;
    }
    int fb_map[13];
    if (okA)      map = mapA;
    else if (okB) map = mapB;
    else if (okC) map = mapC;
    else {
        int next16 = 0, next128 = 0;
        static const int ord16[3]  = {1, 3, 9};
        static const int ord128[7] = {2, 4, 5, 7, 8, 10, 11};
        for (int i = 0; i < 13; i++) fb_map[i] = i;
        for (int p = 0; p < 13 && p < n_in; p++) {
            int s = in_sizes[p];
            if (s == 33554432)      fb_map[0] = p;
            else if (s == 32768)    fb_map[6] = p;
            else if (s == 1)        fb_map[12] = p;
            else if (s == 16384)  { if (next16 < 3)  fb_map[ord16[next16++]]  = p; }
            else if (s == 128)    { if (next128 < 7) fb_map[ord128[next128++]] = p; }
        }
        map = fb_map;
    }

    const float* X  = (const float*)d_in[map[0]];
    const float* Ws = (const float*)d_in[map[1]];
    const float* bs = (const float*)d_in[map[2]];
    const float* Wa = (const float*)d_in[map[3]];
    const float* ba = (const float*)d_in[map[4]];
    const float* va = (const float*)d_in[map[5]];
    const float* Wc = (const float*)d_in[map[6]];
    const float* bc = (const float*)d_in[map[7]];
    const float* vc = (const float*)d_in[map[8]];
    const float* W1 = (const float*)d_in[map[9]];
    const float* b1 = (const float*)d_in[map[10]];
    const float* W2 = (const float*)d_in[map[11]];
    const float* b2 = (const float*)d_in[map[12]];
    float* out = (float*)d_out;

    cudaFuncSetAttribute(proj_ut_mma, cudaFuncAttributeMaxDynamicSharedMemorySize, K1_SMEM);
    cudaFuncSetAttribute(attn2_mma,  cudaFuncAttributeMaxDynamicSharedMemorySize, K3_SMEM);

    prep_weights<<<256, 256>>>(Ws, Wa, Wc);
    proj_ut_mma<<<148, 384, K1_SMEM>>>(X, bs, ba, va);
    softmax_rows<<<BB, 256>>>(0);
    attn2_mma<<<148, 384, K3_SMEM>>>(bc, vc);
    softmax_rows<<<BB, 256>>>(1);
    reduce_hi<<<BB, 256>>>();
    final_mlp<<<BB, 128>>>(W1, b1, W2, b2, out);
}

// round 15
// speedup vs baseline: 2.4661x; 1.0047x over previous
#include <cuda_runtime.h>
#include <cuda_bf16.h>
#include <math.h>
#include <stdint.h>

// Problem constants
#define BB 128
#define NN 2048
#define EE 128
#define MT (BB * NN)   // 262144 total rows
#define NG32 (MT / 32) // 8192 32-row groups

// ---------------- scratch (device globals; no allocation allowed) -----------
__device__ float g_proj[(size_t)MT * EE];   // [M,128]
__device__ float g_ut  [MT];
__device__ float g_at  [MT];
__device__ float g_ut2 [MT];
__device__ float g_prob[MT];
__device__ float g_hi  [BB * EE];

// Packed weight fragments (bf16 hi/lo, per-lane mma fragment order).
// Entry (nb*8+kt)*32+lane = {hi(k,k+1), hi(k+8,k+9), lo(k,k+1), lo(k+8,k+9)}
// with n = 8*nb+gid, k = 16*kt+2*tig.
__device__ uint4 g_WsP[16 * 8 * 32];        // Ws  [128 x 128]  -> 16 n-blocks
__device__ uint4 g_WtP[48 * 8 * 32];        // [Wa; Wc1; Wc2] [384 x 128] -> 48

__device__ __forceinline__ void split2(float x0, float x1,
                                       unsigned &hi, unsigned &lo) {
    __nv_bfloat16 h0 = __float2bfloat16_rn(x0);
    __nv_bfloat16 h1 = __float2bfloat16_rn(x1);
    float r0 = x0 - __bfloat162float(h0);
    float r1 = x1 - __bfloat162float(h1);
    __nv_bfloat162 hh; hh.x = h0; hh.y = h1;
    __nv_bfloat162 ll; ll.x = __float2bfloat16_rn(r0);
                       ll.y = __float2bfloat16_rn(r1);
    hi = *reinterpret_cast<unsigned*>(&hh);
    lo = *reinterpret_cast<unsigned*>(&ll);
}

#define MMA16816(d, a, b0_, b1_) \
  asm volatile("mma.sync.aligned.m16n8k16.row.col.f32.bf16.bf16.f32 " \
    "{%0,%1,%2,%3}, {%4,%5,%6,%7}, {%8,%9}, {%0,%1,%2,%3};" \
    : "+f"(d[0]), "+f"(d[1]), "+f"(d[2]), "+f"(d[3]) \
    : "r"(a[0]), "r"(a[1]), "r"(a[2]), "r"(a[3]), "r"(b0_), "r"(b1_))

// 12 MMAs over 4 independent accumulators (hi*Whi, hi*Wlo, lo*Whi).
#define MMA_GROUP4(ACC, B0, AH, AL, Q0, Q1, Q2, Q3) do { \
    MMA16816(ACC[B0 + 0], AH, Q0.x, Q0.y); \
    MMA16816(ACC[B0 + 1], AH, Q1.x, Q1.y); \
    MMA16816(ACC[B0 + 2], AH, Q2.x, Q2.y); \
    MMA16816(ACC[B0 + 3], AH, Q3.x, Q3.y); \
    MMA16816(ACC[B0 + 0], AH, Q0.z, Q0.w); \
    MMA16816(ACC[B0 + 1], AH, Q1.z, Q1.w); \
    MMA16816(ACC[B0 + 2], AH, Q2.z, Q2.w); \
    MMA16816(ACC[B0 + 3], AH, Q3.z, Q3.w); \
    MMA16816(ACC[B0 + 0], AL, Q0.x, Q0.y); \
    MMA16816(ACC[B0 + 1], AL, Q1.x, Q1.y); \
    MMA16816(ACC[B0 + 2], AL, Q2.x, Q2.y); \
    MMA16816(ACC[B0 + 3], AL, Q3.x, Q3.y); \
} while (0)

// ---------------- weight prep: fp32 -> bf16 hi/lo fragment-packed -----------
__global__ __launch_bounds__(256) void prep_weights(
    const float* __restrict__ Ws, const float* __restrict__ Wa,
    const float* __restrict__ Wc)
{
    int i = blockIdx.x * 256 + threadIdx.x;     // 0..65535 (one uint each)
    int stage = (i >= 16384) ? 1 : 0;
    int rem = stage ? (i - 16384) : i;
    int j    = rem & 3;
    int lane = (rem >> 2) & 31;
    int kt   = (rem >> 7) & 7;
    int nb   = rem >> 10;
    int gid = lane >> 2, tig = lane & 3;
    int n = nb * 8 + gid;
    int k = kt * 16 + ((j & 1) ? 8 : 0) + 2 * tig;
    float w0, w1;
    if (!stage)        { w0 = Ws[n * 128 + k];            w1 = Ws[n * 128 + k + 1]; }
    else if (n < 128)  { w0 = Wa[n * 128 + k];            w1 = Wa[n * 128 + k + 1]; }
    else if (n < 256)  { w0 = Wc[(n - 128) * 256 + k];    w1 = Wc[(n - 128) * 256 + k + 1]; }
    else               { w0 = Wc[(n - 256) * 256 + 128 + k];
                         w1 = Wc[(n - 256) * 256 + 128 + k + 1]; }
    unsigned hi, lo;
    split2(w0, w1, hi, lo);
    unsigned* dst = stage ? (unsigned*)g_WtP : (unsigned*)g_WsP;
    dst[((nb * 8 + kt) * 32 + lane) * 4 + j] = (j < 2) ? hi : lo;
}

// ---------------- K1': proj = X*Ws^T + bs  AND  u_t  (32 rows/warp) ---------
#define K1_SMEM (2 * 16 * 8 * 32 * 16 + 1536)
__global__ __launch_bounds__(256) void proj_ut_mma(
    const float* __restrict__ X,  const float* __restrict__ bs,
    const float* __restrict__ ba, const float* __restrict__ va)
{
    extern __shared__ char smem[];
    uint4* sWs = (uint4*)smem;                              // [4096]
    uint4* sWa = (uint4*)(smem + 16 * 8 * 32 * 16);         // [4096]
    float* smbs = (float*)(smem + 2 * 16 * 8 * 32 * 16);
    float* smba = smbs + 128;
    float* smva = smba + 128;
    const int tid = threadIdx.x;
    for (int i = tid; i < 16 * 8 * 32; i += 256) {
        sWs[i] = g_WsP[i];
        sWa[i] = g_WtP[i];              // Wa = first 16 n-blocks of WtP
    }
    if (tid < 128) {
        smbs[tid] = bs[tid];
        smba[tid] = ba[tid];
        smva[tid] = va[tid];
    }
    __syncthreads();

    const int wid = tid >> 5, lane = tid & 31;
    const int gid = lane >> 2, tig = lane & 3;
    const int gstride = gridDim.x * 8;

    for (int g = blockIdx.x * 8 + wid; g < NG32; g += gstride) {
        const size_t base = (size_t)g * 32;
        const size_t rA0 = base + gid,      rA1 = rA0 + 8;   // tile A rows
        const size_t rB0 = base + 16 + gid, rB1 = rB0 + 8;   // tile B rows

        // ---- stage A: proj for both tiles ----
        float acc0[16][4], acc1[16][4];
        #pragma unroll
        for (int b = 0; b < 16; b++) {
            acc0[b][0] = acc0[b][1] = acc0[b][2] = acc0[b][3] = 0.f;
            acc1[b][0] = acc1[b][1] = acc1[b][2] = acc1[b][3] = 0.f;
        }

        #pragma unroll
        for (int kt = 0; kt < 8; kt++) {
            const int k0 = kt * 16;
            unsigned ahA[4], alA[4], ahB[4], alB[4];
            {
                float2 xa = *(const float2*)(X + rA0 * 128 + k0 + 2 * tig);
                float2 xb = *(const float2*)(X + rA1 * 128 + k0 + 2 * tig);
                float2 xc = *(const float2*)(X + rA0 * 128 + k0 + 8 + 2 * tig);
                float2 xd = *(const float2*)(X + rA1 * 128 + k0 + 8 + 2 * tig);
                split2(xa.x, xa.y, ahA[0], alA[0]);
                split2(xb.x, xb.y, ahA[1], alA[1]);
                split2(xc.x, xc.y, ahA[2], alA[2]);
                split2(xd.x, xd.y, ahA[3], alA[3]);
            }
            {
                float2 xa = *(const float2*)(X + rB0 * 128 + k0 + 2 * tig);
                float2 xb = *(const float2*)(X + rB1 * 128 + k0 + 2 * tig);
                float2 xc = *(const float2*)(X + rB0 * 128 + k0 + 8 + 2 * tig);
                float2 xd = *(const float2*)(X + rB1 * 128 + k0 + 8 + 2 * tig);
                split2(xa.x, xa.y, ahB[0], alB[0]);
                split2(xb.x, xb.y, ahB[1], alB[1]);
                split2(xc.x, xc.y, ahB[2], alB[2]);
                split2(xd.x, xd.y, ahB[3], alB[3]);
            }
            #pragma unroll
            for (int bg = 0; bg < 4; bg++) {
                const int b0 = bg * 4;
                uint4 q0 = sWs[((b0 + 0) * 8 + kt) * 32 + lane];
                uint4 q1 = sWs[((b0 + 1) * 8 + kt) * 32 + lane];
                uint4 q2 = sWs[((b0 + 2) * 8 + kt) * 32 + lane];
                uint4 q3 = sWs[((b0 + 3) * 8 + kt) * 32 + lane];
                MMA_GROUP4(acc0, b0, ahA, alA, q0, q1, q2, q3);
                MMA_GROUP4(acc1, b0, ahB, alB, q0, q1, q2, q3);
            }
        }

        // bias + store proj (both tiles)
        #pragma unroll
        for (int b = 0; b < 16; b++) {
            const int c0 = 8 * b + 2 * tig;
            float b0v = smbs[c0], b1v = smbs[c0 + 1];
            acc0[b][0] += b0v; acc0[b][1] += b1v;
            acc0[b][2] += b0v; acc0[b][3] += b1v;
            acc1[b][0] += b0v; acc1[b][1] += b1v;
            acc1[b][2] += b0v; acc1[b][3] += b1v;
            *(float2*)(g_proj + rA0 * 128 + c0) = make_float2(acc0[b][0], acc0[b][1]);
            *(float2*)(g_proj + rA1 * 128 + c0) = make_float2(acc0[b][2], acc0[b][3]);
            *(float2*)(g_proj + rB0 * 128 + c0) = make_float2(acc1[b][0], acc1[b][1]);
            *(float2*)(g_proj + rB1 * 128 + c0) = make_float2(acc1[b][2], acc1[b][3]);
        }

        // ---- stage B: u_t for all 4 row slots ----
        float utA0 = 0.f, utA1 = 0.f, utB0 = 0.f, utB1 = 0.f;
        #pragma unroll 1
        for (int chunk = 0; chunk < 2; chunk++) {
            float d0[8][4], d1[8][4];
            #pragma unroll
            for (int b = 0; b < 8; b++) {
                d0[b][0] = d0[b][1] = d0[b][2] = d0[b][3] = 0.f;
                d1[b][0] = d1[b][1] = d1[b][2] = d1[b][3] = 0.f;
            }
            #pragma unroll
            for (int kt = 0; kt < 8; kt++) {
                unsigned ahA[4], alA[4], ahB[4], alB[4];
                split2(acc0[2*kt  ][0], acc0[2*kt  ][1], ahA[0], alA[0]);
                split2(acc0[2*kt  ][2], acc0[2*kt  ][3], ahA[1], alA[1]);
                split2(acc0[2*kt+1][0], acc0[2*kt+1][1], ahA[2], alA[2]);
                split2(acc0[2*kt+1][2], acc0[2*kt+1][3], ahA[3], alA[3]);
                split2(acc1[2*kt  ][0], acc1[2*kt  ][1], ahB[0], alB[0]);
                split2(acc1[2*kt  ][2], acc1[2*kt  ][3], ahB[1], alB[1]);
                split2(acc1[2*kt+1][0], acc1[2*kt+1][1], ahB[2], alB[2]);
                split2(acc1[2*kt+1][2], acc1[2*kt+1][3], ahB[3], alB[3]);
                #pragma unroll
                for (int bg = 0; bg < 2; bg++) {
                    const int b0 = bg * 4;
                    const int nbb = chunk * 8 + b0;
                    uint4 q0 = sWa[((nbb + 0) * 8 + kt) * 32 + lane];
                    uint4 q1 = sWa[((nbb + 1) * 8 + kt) * 32 + lane];
                    uint4 q2 = sWa[((nbb + 2) * 8 + kt) * 32 + lane];
                    uint4 q3 = sWa[((nbb + 3) * 8 + kt) * 32 + lane];
                    MMA_GROUP4(d0, b0, ahA, alA, q0, q1, q2, q3);
                    MMA_GROUP4(d1, b0, ahB, alB, q0, q1, q2, q3);
                }
            }
            #pragma unroll
            for (int b = 0; b < 8; b++) {
                const int c0 = chunk * 64 + 8 * b + 2 * tig;
                float ba0 = smba[c0], ba1 = smba[c0 + 1];
                float va0 = smva[c0], va1 = smva[c0 + 1];
                utA0 += va0 * tanhf(d0[b][0] + ba0) + va1 * tanhf(d0[b][1] + ba1);
                utA1 += va0 * tanhf(d0[b][2] + ba0) + va1 * tanhf(d0[b][3] + ba1);
                utB0 += va0 * tanhf(d1[b][0] + ba0) + va1 * tanhf(d1[b][1] + ba1);
                utB1 += va0 * tanhf(d1[b][2] + ba0) + va1 * tanhf(d1[b][3] + ba1);
            }
        }
        utA0 += __shfl_xor_sync(0xffffffffu, utA0, 1);
        utA0 += __shfl_xor_sync(0xffffffffu, utA0, 2);
        utA1 += __shfl_xor_sync(0xffffffffu, utA1, 1);
        utA1 += __shfl_xor_sync(0xffffffffu, utA1, 2);
        utB0 += __shfl_xor_sync(0xffffffffu, utB0, 1);
        utB0 += __shfl_xor_sync(0xffffffffu, utB0, 2);
        utB1 += __shfl_xor_sync(0xffffffffu, utB1, 1);
        utB1 += __shfl_xor_sync(0xffffffffu, utB1, 2);
        if (tig == 0) {
            g_ut[rA0] = utA0; g_ut[rA1] = utA1;
            g_ut[rB0] = utB0; g_ut[rB1] = utB1;
        }
    }
}

// ---------------- K3': ut2 = vc.tanh(Wc1*proj + bc + at*(Wc2*proj)) ---------
// 32 rows/warp; each q uint4 feeds 6 MMAs. X1b/X2 never touch DRAM.
#define K3_SMEM (2 * 16 * 8 * 32 * 16 + 1024)
__global__ __launch_bounds__(256) void attn2_mma(
    const float* __restrict__ bc, const float* __restrict__ vc)
{
    extern __shared__ char smem[];
    uint4* sW1 = (uint4*)smem;                              // Wc1 frags
    uint4* sW2 = (uint4*)(smem + 16 * 8 * 32 * 16);         // Wc2 frags
    float* smbc = (float*)(smem + 2 * 16 * 8 * 32 * 16);
    float* smvc = smbc + 128;
    const int tid = threadIdx.x;
    for (int i = tid; i < 16 * 8 * 32; i += 256) {
        sW1[i] = g_WtP[16 * 8 * 32 + i];     // n-blocks 16..31
        sW2[i] = g_WtP[32 * 8 * 32 + i];     // n-blocks 32..47
    }
    if (tid < 128) {
        smbc[tid] = bc[tid];
        smvc[tid] = vc[tid];
    }
    __syncthreads();

    const int wid = tid >> 5, lane = tid & 31;
    const int gid = lane >> 2, tig = lane & 3;
    const int gstride = gridDim.x * 8;

    for (int g = blockIdx.x * 8 + wid; g < NG32; g += gstride) {
        const size_t base = (size_t)g * 32;
        const size_t rA0 = base + gid,      rA1 = rA0 + 8;
        const size_t rB0 = base + 16 + gid, rB1 = rB0 + 8;
        const float aA0 = g_at[rA0], aA1 = g_at[rA1];
        const float aB0 = g_at[rB0], aB1 = g_at[rB1];

        float utA0 = 0.f, utA1 = 0.f, utB0 = 0.f, utB1 = 0.f;
        #pragma unroll 1
        for (int half = 0; half < 2; half++) {
            float d1a[8][4], d1b[8][4], d2a[8][4], d2b[8][4];
            #pragma unroll
            for (int b = 0; b < 8; b++) {
                d1a[b][0] = d1a[b][1] = d1a[b][2] = d1a[b][3] = 0.f;
                d1b[b][0] = d1b[b][1] = d1b[b][2] = d1b[b][3] = 0.f;
                d2a[b][0] = d2a[b][1] = d2a[b][2] = d2a[b][3] = 0.f;
                d2b[b][0] = d2b[b][1] = d2b[b][2] = d2b[b][3] = 0.f;
            }
            #pragma unroll
            for (int kt = 0; kt < 8; kt++) {
                const int k0 = kt * 16;
                unsigned ahA[4], alA[4], ahB[4], alB[4];
                {
                    float2 xa = *(const float2*)(g_proj + rA0 * 128 + k0 + 2 * tig);
                    float2 xb = *(const float2*)(g_proj + rA1 * 128 + k0 + 2 * tig);
                    float2 xc = *(const float2*)(g_proj + rA0 * 128 + k0 + 8 + 2 * tig);
                    float2 xd = *(const float2*)(g_proj + rA1 * 128 + k0 + 8 + 2 * tig);
                    split2(xa.x, xa.y, ahA[0], alA[0]);
                    split2(xb.x, xb.y, ahA[1], alA[1]);
                    split2(xc.x, xc.y, ahA[2], alA[2]);
                    split2(xd.x, xd.y, ahA[3], alA[3]);
                }
                {
                    float2 xa = *(const float2*)(g_proj + rB0 * 128 + k0 + 2 * tig);
                    float2 xb = *(const float2*)(g_proj + rB1 * 128 + k0 + 2 * tig);
                    float2 xc = *(const float2*)(g_proj + rB0 * 128 + k0 + 8 + 2 * tig);
                    float2 xd = *(const float2*)(g_proj + rB1 * 128 + k0 + 8 + 2 * tig);
                    split2(xa.x, xa.y, ahB[0], alB[0]);
                    split2(xb.x, xb.y, ahB[1], alB[1]);
                    split2(xc.x, xc.y, ahB[2], alB[2]);
                    split2(xd.x, xd.y, ahB[3], alB[3]);
                }
                #pragma unroll
                for (int bg = 0; bg < 2; bg++) {
                    const int b0 = bg * 4;
                    const int nbb = half * 8 + b0;
                    uint4 q0 = sW1[((nbb + 0) * 8 + kt) * 32 + lane];
                    uint4 q1 = sW1[((nbb + 1) * 8 + kt) * 32 + lane];
                    uint4 q2 = sW1[((nbb + 2) * 8 + kt) * 32 + lane];
                    uint4 q3 = sW1[((nbb + 3) * 8 + kt) * 32 + lane];
                    MMA_GROUP4(d1a, b0, ahA, alA, q0, q1, q2, q3);
                    MMA_GROUP4(d1b, b0, ahB, alB, q0, q1, q2, q3);
                    uint4 p0 = sW2[((nbb + 0) * 8 + kt) * 32 + lane];
                    uint4 p1 = sW2[((nbb + 1) * 8 + kt) * 32 + lane];
                    uint4 p2 = sW2[((nbb + 2) * 8 + kt) * 32 + lane];
                    uint4 p3 = sW2[((nbb + 3) * 8 + kt) * 32 + lane];
                    MMA_GROUP4(d2a, b0, ahA, alA, p0, p1, p2, p3);
                    MMA_GROUP4(d2b, b0, ahB, alB, p0, p1, p2, p3);
                }
            }
            #pragma unroll
            for (int b = 0; b < 8; b++) {
                const int c0 = half * 64 + 8 * b + 2 * tig;
                float bc0 = smbc[c0], bc1 = smbc[c0 + 1];
                float vc0 = smvc[c0], vc1 = smvc[c0 + 1];
                utA0 += vc0 * tanhf(d1a[b][0] + bc0 + aA0 * d2a[b][0])
                      + vc1 * tanhf(d1a[b][1] + bc1 + aA0 * d2a[b][1]);
                utA1 += vc0 * tanhf(d1a[b][2] + bc0 + aA1 * d2a[b][2])
                      + vc1 * tanhf(d1a[b][3] + bc1 + aA1 * d2a[b][3]);
                utB0 += vc0 * tanhf(d1b[b][0] + bc0 + aB0 * d2b[b][0])
                      + vc1 * tanhf(d1b[b][1] + bc1 + aB0 * d2b[b][1]);
                utB1 += vc0 * tanhf(d1b[b][2] + bc0 + aB1 * d2b[b][2])
                      + vc1 * tanhf(d1b[b][3] + bc1 + aB1 * d2b[b][3]);
            }
        }
        utA0 += __shfl_xor_sync(0xffffffffu, utA0, 1);
        utA0 += __shfl_xor_sync(0xffffffffu, utA0, 2);
        utA1 += __shfl_xor_sync(0xffffffffu, utA1, 1);
        utA1 += __shfl_xor_sync(0xffffffffu, utA1, 2);
        utB0 += __shfl_xor_sync(0xffffffffu, utB0, 1);
        utB0 += __shfl_xor_sync(0xffffffffu, utB0, 2);
        utB1 += __shfl_xor_sync(0xffffffffu, utB1, 1);
        utB1 += __shfl_xor_sync(0xffffffffu, utB1, 2);
        if (tig == 0) {
            g_ut2[rA0] = utA0; g_ut2[rA1] = utA1;
            g_ut2[rB0] = utB0; g_ut2[rB1] = utB1;
        }
    }
}

// ---------------- softmax over N=2048 per batch -----------------------------
__global__ __launch_bounds__(256) void softmax_rows(int which)
{
    const float* u = (which == 0) ? g_ut : g_ut2;
    float* p       = (which == 0) ? g_at : g_prob;
    const int b = blockIdx.x;
    const float* ub = u + (size_t)b * NN;
    float* pb = p + (size_t)b * NN;
    const int tid = threadIdx.x;
    __shared__ float sm[256];

    float mx = -1e30f;
    for (int i = tid; i < NN; i += 256) mx = fmaxf(mx, ub[i]);
    sm[tid] = mx; __syncthreads();
    for (int s = 128; s > 0; s >>= 1) {
        if (tid < s) sm[tid] = fmaxf(sm[tid], sm[tid + s]);
        __syncthreads();
    }
    mx = sm[0]; __syncthreads();

    float sum = 0.f;
    for (int i = tid; i < NN; i += 256) {
        float e = __expf(ub[i] - mx);
        pb[i] = e;
        sum += e;
    }
    sm[tid] = sum; __syncthreads();
    for (int s = 128; s > 0; s >>= 1) {
        if (tid < s) sm[tid] += sm[tid + s];
        __syncthreads();
    }
    float inv = 1.f / sm[0];
    for (int i = tid; i < NN; i += 256) pb[i] *= inv;
}

// ---------------- h_i = sum_n prob * proj ----------------------------------
__global__ __launch_bounds__(256) void reduce_hi()
{
    const int b = blockIdx.x;
    const int e = threadIdx.x & 127;
    const int half = threadIdx.x >> 7;
    float s = 0.f;
    const float* pb = g_prob + (size_t)b * NN;
    const float* prb = g_proj + (size_t)b * NN * 128;
    for (int n = half; n < NN; n += 2)
        s = fmaf(pb[n], prb[(size_t)n * 128 + e], s);
    __shared__ float sm[256];
    sm[threadIdx.x] = s; __syncthreads();
    if (half == 0) g_hi[b * 128 + e] = sm[e] + sm[128 + e];
}

// ---------------- final MLP: v = W2 . relu(W1 h + b1) + b2 ------------------
__global__ __launch_bounds__(128) void final_mlp(
    const float* __restrict__ W1, const float* __restrict__ b1,
    const float* __restrict__ W2, const float* __restrict__ b2,
    float* __restrict__ out)
{
    const int b = blockIdx.x;
    const int e = threadIdx.x;
    __shared__ float h[128];
    __shared__ float sm[128];
    h[e] = g_hi[b * 128 + e];
    __syncthreads();
    float s = b1[e];
    #pragma unroll 8
    for (int k = 0; k < 128; k++) s = fmaf(W1[e * 128 + k], h[k], s);
    sm[e] = fmaxf(s, 0.f) * W2[e];
    __syncthreads();
    for (int st = 64; st > 0; st >>= 1) {
        if (e < st) sm[e] += sm[e + st];
        __syncthreads();
    }
    if (e == 0) out[b] = sm[0] + b2[0];
}

// ---------------- launch ----------------------------------------------------
// Canonical indices: 0 instance,1 W_s,2 b_s,3 W_a,4 b_a,5 v_a,6 W_c,7 b_c,
//                    8 v_c,9 W1,10 b1,11 W2,12 b2
extern "C" void kernel_launch(void* const* d_in, const int* in_sizes, int n_in,
                              void* d_out, int out_size)
{
    static const int sigA[13] = {33554432,16384,128,16384,128,128,32768,128,128,16384,128,128,1};
    static const int mapA[13] = {0,1,2,3,4,5,6,7,8,9,10,11,12};
    static const int sigB[13] = {16384,128,16384,32768,16384,128,1,128,128,128,33554432,128,128};
    static const int mapB[13] = {10,4,9,2,7,11,3,8,12,0,5,1,6};
    static const int sigC[13] = {128,1,128,128,128,33554432,128,128,16384,128,16384,32768,16384};
    static const int mapC[13] = {5,12,4,10,2,6,11,3,7,8,0,9,1};

    const int* map = mapA;
    bool okA = true, okB = true, okC = true;
    for (int i = 0; i < 13 && i < n_in; i++) {
        if (in_sizes[i] != sigA[i]) okA = false;
        if (in_sizes[i] != sigB[i]) okB = false;
        if (in_sizes[i] != sigC[i]) okC = false;
    }
    int fb_map[13];
    if (okA)      map = mapA;
    else if (okB) map = mapB;
    else if (okC) map = mapC;
    else {
        int next16 = 0, next128 = 0;
        static const int ord16[3]  = {1, 3, 9};
        static const int ord128[7] = {2, 4, 5, 7, 8, 10, 11};
        for (int i = 0; i < 13; i++) fb_map[i] = i;
        for (int p = 0; p < 13 && p < n_in; p++) {
            int s = in_sizes[p];
            if (s == 33554432)      fb_map[0] = p;
            else if (s == 32768)    fb_map[6] = p;
            else if (s == 1)        fb_map[12] = p;
            else if (s == 16384)  { if (next16 < 3)  fb_map[ord16[next16++]]  = p; }
            else if (s == 128)    { if (next128 < 7) fb_map[ord128[next128++]] = p; }
        }
        map = fb_map;
    }

    const float* X  = (const float*)d_in[map[0]];
    const float* Ws = (const float*)d_in[map[1]];
    const float* bs = (const float*)d_in[map[2]];
    const float* Wa = (const float*)d_in[map[3]];
    const float* ba = (const float*)d_in[map[4]];
    const float* va = (const float*)d_in[map[5]];
    const float* Wc = (const float*)d_in[map[6]];
    const float* bc = (const float*)d_in[map[7]];
    const float* vc = (const float*)d_in[map[8]];
    const float* W1 = (const float*)d_in[map[9]];
    const float* b1 = (const float*)d_in[map[10]];
    const float* W2 = (const float*)d_in[map[11]];
    const float* b2 = (const float*)d_in[map[12]];
    float* out = (float*)d_out;

    cudaFuncSetAttribute(proj_ut_mma, cudaFuncAttributeMaxDynamicSharedMemorySize, K1_SMEM);
    cudaFuncSetAttribute(attn2_mma,  cudaFuncAttributeMaxDynamicSharedMemorySize, K3_SMEM);

    prep_weights<<<256, 256>>>(Ws, Wa, Wc);
    proj_ut_mma<<<148, 256, K1_SMEM>>>(X, bs, ba, va);
    softmax_rows<<<BB, 256>>>(0);
    attn2_mma<<<148, 256, K3_SMEM>>>(bc, vc);
    softmax_rows<<<BB, 256>>>(1);
    reduce_hi<<<BB, 256>>>();
    final_mlp<<<BB, 128>>>(W1, b1, W2, b2, out);
}